// round 4
// baseline (speedup 1.0000x reference)
#include <cuda_runtime.h>
#include <math.h>

#define Bn 8
#define Ln 2048
#define Dn 512
#define Mn 8
#define KHn 256
#define BMn 64
#define Tn (Bn*Ln)

// ---------------- scratch ----------------
__device__ float g_W1  [(size_t)BMn*Ln*KHn];    // [bm][l][k]
__device__ float g_W2T [(size_t)BMn*KHn*Ln];    // [bm][k][l]
__device__ float g_part[(size_t)BMn*8*64*KHn];  // [bm*8+sp][d][k]
__device__ float g_out1T[(size_t)BMn*KHn*64];   // [bm][k][d]
__device__ float g_mixpre[(size_t)Tn*Dn];
__device__ float g_mix [(size_t)Tn*Dn];
__device__ float g_ln1 [(size_t)Tn*Dn];
__device__ float g_glu [(size_t)Tn*Dn];
__device__ float g_dw  [(size_t)Tn*Dn];
__device__ float g_act [(size_t)Tn*Dn];

__device__ __forceinline__ float gelu_f(float v){
  return 0.5f*v*(1.0f+erff(v*0.70710678118654752f));
}

// ---------------- K1: fused hypernet MLPs ----------------
__global__ void __launch_bounds__(256) k_pmlp(
    const float* __restrict__ x,
    const float* __restrict__ w1f1w, const float* __restrict__ w1f1b,
    const float* __restrict__ w1f2w, const float* __restrict__ w1f2b,
    const float* __restrict__ w2f1w, const float* __restrict__ w2f1b,
    const float* __restrict__ w2f2w, const float* __restrict__ w2f2b)
{
  extern __shared__ float sm[];
  float* xs = sm;             // 64 x 68
  float* ws = sm + 4352;      // 2 x 64 x 68
  float* hs = ws + 8704;      // 2 x 64 x 68
  float* ys = hs + 8704;      // 64 x 68
  const int m = blockIdx.y, t0 = blockIdx.x*64;
  const int b = t0 >> 11, l0 = t0 & (Ln-1), bm = b*Mn + m;
  const int tid = threadIdx.x;
  const float c0 = -9.210340371976184f / 512.0f;

  #pragma unroll
  for (int i = 0; i < 16; i++) {
    int idx = i*256 + tid, tok = idx>>6, f = idx&63;
    int ch = m*64 + f, l = l0 + tok;
    float ang = (float)l * expf((float)(ch & ~1) * c0);
    float pe  = (ch & 1) ? cosf(ang) : sinf(ang);
    xs[tok*68+f] = x[(size_t)(b*Ln + l)*Dn + ch] + pe;
  }
  #pragma unroll
  for (int i = 0; i < 32; i++) {
    int idx = i*256 + tid, net = idx>>12, r = idx&4095;
    int hid = r>>6, f = r&63;
    const float* w = net ? w2f1w : w1f1w;
    ws[net*4352 + hid*68 + f] = w[m*4096 + hid*64 + f];
  }
  __syncthreads();
  // phase A: hidden = gelu(fc1@x+b1), 2 tokens per thread
  #pragma unroll
  for (int i = 0; i < 16; i++) {
    int idx = i*256 + tid;
    int net = idx>>11, tok2 = (idx>>6)&31, hid = idx&63;
    int ta = tok2*2, tb = ta+1;
    const float* bp = net ? w2f1b : w1f1b;
    float acc0 = bp[m*64+hid], acc1 = acc0;
    const float4* wr = (const float4*)(ws + net*4352 + hid*68);
    const float4* xa = (const float4*)(xs + ta*68);
    const float4* xb = (const float4*)(xs + tb*68);
    #pragma unroll
    for (int q = 0; q < 16; q++) {
      float4 w4 = wr[q], a4 = xa[q], b4 = xb[q];
      acc0 += a4.x*w4.x + a4.y*w4.y + a4.z*w4.z + a4.w*w4.w;
      acc1 += b4.x*w4.x + b4.y*w4.y + b4.z*w4.z + b4.w*w4.w;
    }
    hs[net*4352 + ta*68 + hid] = gelu_f(acc0);
    hs[net*4352 + tb*68 + hid] = gelu_f(acc1);
  }
  __syncthreads();
  // phase B: out = fc2@hidden + b2, in 4 chunks of 64 k
  for (int kc = 0; kc < 4; kc++) {
    #pragma unroll
    for (int i = 0; i < 32; i++) {
      int idx = i*256 + tid, net = idx>>12, r = idx&4095;
      int kk = r>>6, h = r&63;
      const float* w = net ? w2f2w : w1f2w;
      ws[net*4352 + kk*68 + h] = w[m*16384 + (kc*64+kk)*64 + h];
    }
    __syncthreads();
    #pragma unroll
    for (int i = 0; i < 16; i++) {
      int idx = i*256 + tid;
      int net = idx>>11, tok2 = (idx>>6)&31, kk = idx&63;
      int ta = tok2*2, tb = ta+1;
      const float* bp = net ? w2f2b : w1f2b;
      float acc0 = bp[m*256 + kc*64 + kk], acc1 = acc0;
      const float4* wr = (const float4*)(ws + net*4352 + kk*68);
      const float4* ha = (const float4*)(hs + net*4352 + ta*68);
      const float4* hb = (const float4*)(hs + net*4352 + tb*68);
      #pragma unroll
      for (int q = 0; q < 16; q++) {
        float4 w4 = wr[q], a4 = ha[q], b4 = hb[q];
        acc0 += a4.x*w4.x + a4.y*w4.y + a4.z*w4.z + a4.w*w4.w;
        acc1 += b4.x*w4.x + b4.y*w4.y + b4.z*w4.z + b4.w*w4.w;
      }
      if (net == 0) {
        g_W1[(size_t)(bm*Ln + l0+ta)*KHn + kc*64+kk] = acc0;
        g_W1[(size_t)(bm*Ln + l0+tb)*KHn + kc*64+kk] = acc1;
      } else {
        ys[ta*68+kk] = acc0;
        ys[tb*68+kk] = acc1;
      }
    }
    __syncthreads();
    #pragma unroll
    for (int i = 0; i < 16; i++) {
      int idx = i*256 + tid, tok = idx&63, kk = idx>>6;
      g_W2T[(size_t)(bm*KHn + kc*64+kk)*Ln + l0 + tok] = ys[tok*68+kk];
    }
    __syncthreads();
  }
}

// ---------------- K2: bmm1 split-K ----------------
__global__ void __launch_bounds__(256) k_gemm1(const float* __restrict__ x){
  __shared__ float xs[32*65];
  __shared__ float wsm[32*257];
  const int bm = blockIdx.x, sp = blockIdx.y;
  const int b = bm>>3, m = bm&7;
  const int tid = threadIdx.x, tx = tid&15, ty = tid>>4;
  float acc[4][16];
  #pragma unroll
  for (int a=0;a<4;a++)
    #pragma unroll
    for (int s=0;s<16;s++) acc[a][s]=0.f;
  const int lbase = sp*256;
  for (int lc = 0; lc < 256; lc += 32) {
    #pragma unroll
    for (int i=0;i<8;i++){ int idx=i*256+tid, l=idx>>6, d=idx&63;
      xs[l*65+d] = x[(size_t)(b*Ln + lbase+lc+l)*Dn + m*64 + d]; }
    #pragma unroll
    for (int i=0;i<32;i++){ int idx=i*256+tid, l=idx>>8, k=idx&255;
      wsm[l*257+k] = g_W1[(size_t)(bm*Ln + lbase+lc+l)*KHn + k]; }
    __syncthreads();
    #pragma unroll 4
    for (int l=0;l<32;l++){
      float a0=xs[l*65+ty*4+0], a1=xs[l*65+ty*4+1];
      float a2=xs[l*65+ty*4+2], a3=xs[l*65+ty*4+3];
      #pragma unroll
      for (int s=0;s<16;s++){
        float bv = wsm[l*257 + tx + s*16];
        acc[0][s]+=a0*bv; acc[1][s]+=a1*bv; acc[2][s]+=a2*bv; acc[3][s]+=a3*bv;
      }
    }
    __syncthreads();
  }
  #pragma unroll
  for (int a=0;a<4;a++)
    #pragma unroll
    for (int s=0;s<16;s++)
      g_part[(size_t)((bm*8+sp)*64 + ty*4+a)*KHn + tx + s*16] = acc[a][s];
}

// ---------------- K2b: reduce + gelu, store [bm][k][d] ----------------
__global__ void k_red1(){
  int g = blockIdx.x*256 + threadIdx.x;
  int bm = g>>14, r = g&16383;
  int k = r&255, d = r>>8;
  float s = 0.f;
  #pragma unroll
  for (int sp=0;sp<8;sp++)
    s += g_part[(size_t)((bm*8+sp)*64 + d)*KHn + k];
  g_out1T[(size_t)bm*16384 + k*64 + d] = gelu_f(s);
}

// ---------------- K3: bmm2 ----------------
__global__ void __launch_bounds__(256) k_gemm2(){
  __shared__ float sm2[128*65];
  float* As = sm2;
  float* Bs = sm2 + 32*65;
  const int bm = blockIdx.x, l0 = blockIdx.y*128;
  const int tid=threadIdx.x, tx=tid&15, ty=tid>>4;
  float acc[4][8];
  #pragma unroll
  for (int a=0;a<4;a++)
    #pragma unroll
    for (int s=0;s<8;s++) acc[a][s]=0.f;
  for (int kc=0;kc<256;kc+=32){
    #pragma unroll
    for (int i=0;i<8;i++){ int idx=i*256+tid, d=idx&63, k=idx>>6;
      As[k*65+d] = g_out1T[(size_t)bm*16384 + (kc+k)*64 + d]; }
    #pragma unroll
    for (int i=0;i<16;i++){ int idx=i*256+tid, l=idx&127, k=idx>>7;
      Bs[k*129+l] = g_W2T[(size_t)(bm*KHn + kc+k)*Ln + l0+l]; }
    __syncthreads();
    #pragma unroll 4
    for (int k=0;k<32;k++){
      float a0=As[k*65+ty*4+0], a1=As[k*65+ty*4+1];
      float a2=As[k*65+ty*4+2], a3=As[k*65+ty*4+3];
      #pragma unroll
      for (int s=0;s<8;s++){
        float bv=Bs[k*129+tx+s*16];
        acc[0][s]+=a0*bv; acc[1][s]+=a1*bv; acc[2][s]+=a2*bv; acc[3][s]+=a3*bv;
      }
    }
    __syncthreads();
  }
  float* Cs = sm2;
  __syncthreads();
  #pragma unroll
  for (int a=0;a<4;a++)
    #pragma unroll
    for (int s=0;s<8;s++)
      Cs[(tx+s*16)*65 + ty*4+a] = acc[a][s];
  __syncthreads();
  const int b = bm>>3, m = bm&7;
  #pragma unroll
  for (int i=0;i<32;i++){ int idx=i*256+tid, d=idx&63, l=idx>>6;
    g_mixpre[(size_t)(b*Ln + l0+l)*Dn + m*64 + d] = Cs[l*65+d]; }
}

// ---------------- block reduce (128 thr) ----------------
__device__ __forceinline__ float blkSum128(float v){
  __shared__ float red[4];
  #pragma unroll
  for (int o=16;o>0;o>>=1) v += __shfl_down_sync(0xffffffffu, v, o);
  if ((threadIdx.x & 31) == 0) red[threadIdx.x>>5] = v;
  __syncthreads();
  float s = red[0]+red[1]+red[2]+red[3];
  __syncthreads();
  return s;
}

// ---------------- K4: mix = LN(mixpre); ln1 = LN(mix) ----------------
__global__ void __launch_bounds__(128) k_lnmix(
    const float* __restrict__ gm, const float* __restrict__ bb0,
    const float* __restrict__ g1, const float* __restrict__ b1){
  const int t = blockIdx.x, tid = threadIdx.x;
  float v[4];
  #pragma unroll
  for (int i=0;i<4;i++) v[i] = g_mixpre[(size_t)t*Dn + tid + i*128];
  float mean = blkSum128(v[0]+v[1]+v[2]+v[3]) * (1.f/512.f);
  float q = 0.f;
  #pragma unroll
  for (int i=0;i<4;i++){ float d=v[i]-mean; q += d*d; }
  float inv = rsqrtf(blkSum128(q)*(1.f/512.f) + 1e-5f);
  float mv[4];
  #pragma unroll
  for (int i=0;i<4;i++){
    int c = tid + i*128;
    mv[i] = (v[i]-mean)*inv*gm[c] + bb0[c];
    g_mix[(size_t)t*Dn + c] = mv[i];
  }
  float mean2 = blkSum128(mv[0]+mv[1]+mv[2]+mv[3]) * (1.f/512.f);
  float q2 = 0.f;
  #pragma unroll
  for (int i=0;i<4;i++){ float d=mv[i]-mean2; q2 += d*d; }
  float inv2 = rsqrtf(blkSum128(q2)*(1.f/512.f) + 1e-5f);
  #pragma unroll
  for (int i=0;i<4;i++){
    int c = tid + i*128;
    g_ln1[(size_t)t*Dn + c] = (mv[i]-mean2)*inv2*g1[c] + b1[c];
  }
}

// ---------------- K5: bneck 1x1 + GLU ----------------
__global__ void __launch_bounds__(256) k_bneck(
    const float* __restrict__ bw, const float* __restrict__ bb){
  __shared__ float smm[64*129];
  float* As = smm;
  float* Bs = smm + 32*65;
  const int t0 = blockIdx.x*64, e0 = blockIdx.y*64;
  const int tid = threadIdx.x, tx = tid&15, ty = tid>>4;
  float acc[4][8];
  #pragma unroll
  for (int a=0;a<4;a++)
    #pragma unroll
    for (int s=0;s<8;s++) acc[a][s]=0.f;
  for (int kc=0;kc<512;kc+=32){
    #pragma unroll
    for (int i=0;i<8;i++){ int idx=i*256+tid, k=idx&31, t=idx>>5;
      As[k*65+t] = g_ln1[(size_t)(t0+t)*Dn + kc+k]; }
    #pragma unroll
    for (int i=0;i<16;i++){ int idx=i*256+tid, k=idx&31, e=idx>>5;
      int er = (e<64) ? (e0+e) : (512 + e0 + (e-64));
      Bs[k*129+e] = bw[(size_t)er*Dn + kc+k]; }
    __syncthreads();
    #pragma unroll 4
    for (int k=0;k<32;k++){
      float a0=As[k*65+ty*4+0], a1=As[k*65+ty*4+1];
      float a2=As[k*65+ty*4+2], a3=As[k*65+ty*4+3];
      #pragma unroll
      for (int s=0;s<8;s++){
        float bv=Bs[k*129+tx+s*16];
        acc[0][s]+=a0*bv; acc[1][s]+=a1*bv; acc[2][s]+=a2*bv; acc[3][s]+=a3*bv;
      }
    }
    __syncthreads();
  }
  float* ysm = smm;
  __syncthreads();
  #pragma unroll
  for (int a=0;a<4;a++)
    #pragma unroll
    for (int s=0;s<8;s++)
      ysm[(ty*4+a)*129 + tx+s*16] = acc[a][s];
  __syncthreads();
  #pragma unroll
  for (int i=0;i<16;i++){ int idx=i*256+tid, j=idx&63, t=idx>>6;
    float ya = ysm[t*129+j]    + bb[e0+j];
    float yb = ysm[t*129+64+j] + bb[512+e0+j];
    g_glu[(size_t)(t0+t)*Dn + e0+j] = ya * (1.f/(1.f+expf(-yb)));
  }
}

// ---------------- K6: depthwise conv ----------------
__global__ void __launch_bounds__(256) k_dwconv(
    const float* __restrict__ dww, const float* __restrict__ dwb){
  __shared__ float gs[94*64];
  const int b = blockIdx.z, c0 = blockIdx.y*64, l0 = blockIdx.x*64;
  const int tid = threadIdx.x, c = tid&63, lw = tid>>6;
  float w[31];
  #pragma unroll
  for (int j=0;j<31;j++) w[j] = dww[(c0+c)*31 + j];
  for (int i = tid; i < 94*64; i += 256){
    int row = i>>6, cc = i&63;
    int l = l0 - 15 + row;
    gs[i] = (l>=0 && l<Ln) ? g_glu[(size_t)(b*Ln + l)*Dn + c0+cc] : 0.f;
  }
  __syncthreads();
  float bv = dwb[c0+c];
  for (int lo=0; lo<16; lo++){
    int l = lo*4 + lw;
    float acc = bv;
    #pragma unroll
    for (int j=0;j<31;j++) acc += gs[(l+j)*64 + c] * w[j];
    g_dw[(size_t)(b*Ln + l0+l)*Dn + c0+c] = acc;
  }
}

// ---------------- K7: act = gelu(LN(dw)) ----------------
__global__ void __launch_bounds__(128) k_ln2gelu(
    const float* __restrict__ g2, const float* __restrict__ b2){
  const int t = blockIdx.x, tid = threadIdx.x;
  float v[4];
  #pragma unroll
  for (int i=0;i<4;i++) v[i] = g_dw[(size_t)t*Dn + tid + i*128];
  float mean = blkSum128(v[0]+v[1]+v[2]+v[3]) * (1.f/512.f);
  float q = 0.f;
  #pragma unroll
  for (int i=0;i<4;i++){ float d=v[i]-mean; q += d*d; }
  float inv = rsqrtf(blkSum128(q)*(1.f/512.f) + 1e-5f);
  #pragma unroll
  for (int i=0;i<4;i++){
    int c = tid + i*128;
    g_act[(size_t)t*Dn + c] = gelu_f((v[i]-mean)*inv*g2[c] + b2[c]);
  }
}

// ---------------- K8: final linear + residual ----------------
__global__ void __launch_bounds__(256) k_lin(
    const float* __restrict__ lw, const float* __restrict__ lb,
    float* __restrict__ out){
  __shared__ float smm[64*129];
  float* As = smm;
  float* Bs = smm + 32*65;
  const int t0 = blockIdx.x*64, d0 = blockIdx.y*128;
  const int tid = threadIdx.x, tx = tid&15, ty = tid>>4;
  float acc[4][8];
  #pragma unroll
  for (int a=0;a<4;a++)
    #pragma unroll
    for (int s=0;s<8;s++) acc[a][s]=0.f;
  for (int kc=0;kc<512;kc+=32){
    #pragma unroll
    for (int i=0;i<8;i++){ int idx=i*256+tid, k=idx&31, t=idx>>5;
      As[k*65+t] = g_act[(size_t)(t0+t)*Dn + kc+k]; }
    #pragma unroll
    for (int i=0;i<16;i++){ int idx=i*256+tid, k=idx&31, e=idx>>5;
      Bs[k*129+e] = lw[(size_t)(d0+e)*Dn + kc+k]; }
    __syncthreads();
    #pragma unroll 4
    for (int k=0;k<32;k++){
      float a0=As[k*65+ty*4+0], a1=As[k*65+ty*4+1];
      float a2=As[k*65+ty*4+2], a3=As[k*65+ty*4+3];
      #pragma unroll
      for (int s=0;s<8;s++){
        float bv=Bs[k*129+tx+s*16];
        acc[0][s]+=a0*bv; acc[1][s]+=a1*bv; acc[2][s]+=a2*bv; acc[3][s]+=a3*bv;
      }
    }
    __syncthreads();
  }
  float* ysm = smm;
  __syncthreads();
  #pragma unroll
  for (int a=0;a<4;a++)
    #pragma unroll
    for (int s=0;s<8;s++)
      ysm[(ty*4+a)*129 + tx+s*16] = acc[a][s];
  __syncthreads();
  #pragma unroll
  for (int i=0;i<32;i++){ int idx=i*256+tid, e=idx&127, t=idx>>7;
    size_t o = (size_t)(t0+t)*Dn + d0+e;
    out[o] = g_mix[o] + ysm[t*129+e] + lb[d0+e];
  }
}

// ---------------- launch ----------------
extern "C" void kernel_launch(void* const* d_in, const int* in_sizes, int n_in,
                              void* d_out, int out_size) {
  const float* x      = (const float*)d_in[0];
  const float* w1f1w  = (const float*)d_in[1];
  const float* w1f1b  = (const float*)d_in[2];
  const float* w1f2w  = (const float*)d_in[3];
  const float* w1f2b  = (const float*)d_in[4];
  const float* w2f1w  = (const float*)d_in[5];
  const float* w2f1b  = (const float*)d_in[6];
  const float* w2f2w  = (const float*)d_in[7];
  const float* w2f2b  = (const float*)d_in[8];
  const float* lnmg   = (const float*)d_in[9];
  const float* lnmb   = (const float*)d_in[10];
  const float* ln1g   = (const float*)d_in[11];
  const float* ln1b   = (const float*)d_in[12];
  const float* bw     = (const float*)d_in[13];
  const float* bb     = (const float*)d_in[14];
  const float* dww    = (const float*)d_in[15];
  const float* dwb    = (const float*)d_in[16];
  const float* ln2g   = (const float*)d_in[17];
  const float* ln2b   = (const float*)d_in[18];
  const float* lw     = (const float*)d_in[19];
  const float* lb     = (const float*)d_in[20];
  float* out = (float*)d_out;

  const int pmlp_smem = 26112 * 4;
  cudaFuncSetAttribute(k_pmlp, cudaFuncAttributeMaxDynamicSharedMemorySize, pmlp_smem);

  k_pmlp<<<dim3(Tn/64, Mn), 256, pmlp_smem>>>(x, w1f1w, w1f1b, w1f2w, w1f2b,
                                              w2f1w, w2f1b, w2f2w, w2f2b);
  k_gemm1<<<dim3(BMn, 8), 256>>>(x);
  k_red1<<<4096, 256>>>();
  k_gemm2<<<dim3(BMn, 16), 256>>>();
  k_lnmix<<<Tn, 128>>>(lnmg, lnmb, ln1g, ln1b);
  k_bneck<<<dim3(Tn/64, 8), 256>>>(bw, bb);
  k_dwconv<<<dim3(32, 8, 8), 256>>>(dww, dwb);
  k_ln2gelu<<<Tn, 128>>>(ln2g, ln2b);
  k_lin<<<dim3(Tn/64, 4), 256>>>(lw, lb, out);
}

// round 5
// speedup vs baseline: 1.4706x; 1.4706x over previous
#include <cuda_runtime.h>
#include <math.h>

#define Bn 8
#define Ln 2048
#define Dn 512
#define Mn 8
#define KHn 256
#define BMn 64
#define Tn (Bn*Ln)

// ---------------- scratch ----------------
__device__ float g_W1  [(size_t)BMn*Ln*KHn];    // [bm][l][k]
__device__ float g_W2T [(size_t)BMn*KHn*Ln];    // [bm][k][l]
__device__ float g_part[(size_t)BMn*8*64*KHn];  // [bm*8+sp][d][k]
__device__ float g_out1T[(size_t)BMn*KHn*64];   // [bm][k][d]
__device__ float g_mixpre[(size_t)Tn*Dn];
__device__ float g_mix [(size_t)Tn*Dn];
__device__ float g_ln1 [(size_t)Tn*Dn];
__device__ float g_glu [(size_t)Tn*Dn];
__device__ float g_dw  [(size_t)Tn*Dn];
__device__ float g_act [(size_t)Tn*Dn];

__device__ __forceinline__ float gelu_f(float v){
  return 0.5f*v*(1.0f+erff(v*0.70710678118654752f));
}

// ---------------- K1: fused hypernet MLPs ----------------
// smem: xs/ys 4352 | ws 8704 | hs 8704  = 21760 floats (87040 B)
__global__ void __launch_bounds__(256) k_pmlp(
    const float* __restrict__ x,
    const float* __restrict__ w1f1w, const float* __restrict__ w1f1b,
    const float* __restrict__ w1f2w, const float* __restrict__ w1f2b,
    const float* __restrict__ w2f1w, const float* __restrict__ w2f1b,
    const float* __restrict__ w2f2w, const float* __restrict__ w2f2b)
{
  extern __shared__ float sm[];
  float* xs = sm;             // 64 x 68 (also reused as ys staging in phase B)
  float* ws = sm + 4352;      // 2 x 64 x 68
  float* hs = ws + 8704;      // 2 x 64 x 68
  const int m = blockIdx.y, t0 = blockIdx.x*64;
  const int b = t0 >> 11, l0 = t0 & (Ln-1), bm = b*Mn + m;
  const int tid = threadIdx.x;
  const float c0 = -9.210340371976184f / 512.0f;

  #pragma unroll
  for (int i = 0; i < 16; i++) {
    int idx = i*256 + tid, tok = idx>>6, f = idx&63;
    int ch = m*64 + f, l = l0 + tok;
    float ang = (float)l * expf((float)(ch & ~1) * c0);
    float pe  = (ch & 1) ? cosf(ang) : sinf(ang);
    xs[tok*68+f] = x[(size_t)(b*Ln + l)*Dn + ch] + pe;
  }
  #pragma unroll
  for (int i = 0; i < 32; i++) {
    int idx = i*256 + tid, net = idx>>12, r = idx&4095;
    int hid = r>>6, f = r&63;
    const float* w = net ? w2f1w : w1f1w;
    ws[net*4352 + hid*68 + f] = w[m*4096 + hid*64 + f];
  }
  __syncthreads();
  // phase A: hidden = gelu(fc1@x+b1), 2x2 (hid x tok) micro
  #pragma unroll
  for (int i = 0; i < 8; i++) {
    int idx = i*256 + tid;
    int net = idx>>10, hp = (idx>>5)&31, tp = idx&31;
    int h0 = hp*2, ta = tp*2;
    const float* bp = net ? w2f1b : w1f1b;
    float b0 = bp[m*64+h0], b1 = bp[m*64+h0+1];
    float a00=b0, a01=b0, a10=b1, a11=b1;
    const float4* w0r=(const float4*)(ws + net*4352 + h0*68);
    const float4* w1r=(const float4*)(ws + net*4352 + (h0+1)*68);
    const float4* xa =(const float4*)(xs + ta*68);
    const float4* xb =(const float4*)(xs + (ta+1)*68);
    #pragma unroll
    for (int q = 0; q < 16; q++) {
      float4 w0=w0r[q], w1=w1r[q], va=xa[q], vb=xb[q];
      a00 += va.x*w0.x+va.y*w0.y+va.z*w0.z+va.w*w0.w;
      a01 += vb.x*w0.x+vb.y*w0.y+vb.z*w0.z+vb.w*w0.w;
      a10 += va.x*w1.x+va.y*w1.y+va.z*w1.z+va.w*w1.w;
      a11 += vb.x*w1.x+vb.y*w1.y+vb.z*w1.z+vb.w*w1.w;
    }
    hs[net*4352 + ta*68     + h0  ] = gelu_f(a00);
    hs[net*4352 + (ta+1)*68 + h0  ] = gelu_f(a01);
    hs[net*4352 + ta*68     + h0+1] = gelu_f(a10);
    hs[net*4352 + (ta+1)*68 + h0+1] = gelu_f(a11);
  }
  __syncthreads();
  // phase B: out = fc2@hidden + b2, in 4 chunks of 64 k, per-net staging in xs
  float* ys = xs;  // xs no longer needed
  for (int kc = 0; kc < 4; kc++) {
    #pragma unroll
    for (int i = 0; i < 32; i++) {
      int idx = i*256 + tid, net = idx>>12, r = idx&4095;
      int kk = r>>6, h = r&63;
      const float* w = net ? w2f2w : w1f2w;
      ws[net*4352 + kk*68 + h] = w[m*16384 + (kc*64+kk)*64 + h];
    }
    __syncthreads();
    for (int net = 0; net < 2; net++) {
      #pragma unroll
      for (int i = 0; i < 4; i++) {
        int idx = i*256 + tid;
        int kp = idx>>5, tp = idx&31;
        int k0 = kp*2, ta = tp*2;
        const float* bp = net ? w2f2b : w1f2b;
        float b0 = bp[m*256 + kc*64 + k0], b1 = bp[m*256 + kc*64 + k0+1];
        float a00=b0, a01=b0, a10=b1, a11=b1;
        const float4* w0r=(const float4*)(ws + net*4352 + k0*68);
        const float4* w1r=(const float4*)(ws + net*4352 + (k0+1)*68);
        const float4* ha =(const float4*)(hs + net*4352 + ta*68);
        const float4* hb =(const float4*)(hs + net*4352 + (ta+1)*68);
        #pragma unroll
        for (int q = 0; q < 16; q++) {
          float4 w0=w0r[q], w1=w1r[q], va=ha[q], vb=hb[q];
          a00 += va.x*w0.x+va.y*w0.y+va.z*w0.z+va.w*w0.w;
          a01 += vb.x*w0.x+vb.y*w0.y+vb.z*w0.z+vb.w*w0.w;
          a10 += va.x*w1.x+va.y*w1.y+va.z*w1.z+va.w*w1.w;
          a11 += vb.x*w1.x+vb.y*w1.y+vb.z*w1.z+vb.w*w1.w;
        }
        ys[ta*68     + k0  ] = a00;
        ys[(ta+1)*68 + k0  ] = a01;
        ys[ta*68     + k0+1] = a10;
        ys[(ta+1)*68 + k0+1] = a11;
      }
      __syncthreads();
      if (net == 0) {
        #pragma unroll
        for (int i = 0; i < 16; i++) {
          int idx = i*256 + tid, kk = idx&63, tok = idx>>6;
          g_W1[(size_t)(bm*Ln + l0+tok)*KHn + kc*64+kk] = ys[tok*68+kk];
        }
      } else {
        #pragma unroll
        for (int i = 0; i < 16; i++) {
          int idx = i*256 + tid, tok = idx&63, kk = idx>>6;
          g_W2T[(size_t)(bm*KHn + kc*64+kk)*Ln + l0 + tok] = ys[tok*68+kk];
        }
      }
      __syncthreads();
    }
  }
}

// ---------------- K2: bmm1 split-K, tile 64d x 256k, 8x8 micro ----------------
__global__ void __launch_bounds__(256) k_gemm1(const float* __restrict__ x){
  __shared__ float As[32*68];    // [l][d]
  __shared__ float Bs[32*260];   // [l][k]
  const int bm = blockIdx.x, sp = blockIdx.y;
  const int b = bm>>3, m = bm&7;
  const int tid = threadIdx.x, tx = tid&31, ty = tid>>5;
  float acc[8][8];
  #pragma unroll
  for (int r=0;r<8;r++)
    #pragma unroll
    for (int c=0;c<8;c++) acc[r][c]=0.f;
  const int lbase = sp*256;
  for (int lc = 0; lc < 256; lc += 32) {
    #pragma unroll
    for (int i=0;i<2;i++){ int idx=i*256+tid, l=idx>>4, dq=idx&15;
      *(float4*)&As[l*68+dq*4] =
        *(const float4*)&x[(size_t)(b*Ln + lbase+lc+l)*Dn + m*64 + dq*4]; }
    #pragma unroll
    for (int i=0;i<8;i++){ int idx=i*256+tid, l=idx>>6, kq=idx&63;
      *(float4*)&Bs[l*260+kq*4] =
        *(const float4*)&g_W1[(size_t)(bm*Ln + lbase+lc+l)*KHn + kq*4]; }
    __syncthreads();
    #pragma unroll 2
    for (int l=0;l<32;l++){
      float4 a0 = *(const float4*)&As[l*68 + ty*8];
      float4 a1 = *(const float4*)&As[l*68 + ty*8 + 4];
      float4 b0 = *(const float4*)&Bs[l*260 + tx*4];
      float4 b1 = *(const float4*)&Bs[l*260 + 128 + tx*4];
      float av[8] = {a0.x,a0.y,a0.z,a0.w,a1.x,a1.y,a1.z,a1.w};
      float bv[8] = {b0.x,b0.y,b0.z,b0.w,b1.x,b1.y,b1.z,b1.w};
      #pragma unroll
      for (int r=0;r<8;r++)
        #pragma unroll
        for (int c=0;c<8;c++) acc[r][c] += av[r]*bv[c];
    }
    __syncthreads();
  }
  #pragma unroll
  for (int r=0;r<8;r++){
    size_t base = (size_t)((bm*8+sp)*64 + ty*8+r)*KHn;
    *(float4*)&g_part[base + tx*4]       = make_float4(acc[r][0],acc[r][1],acc[r][2],acc[r][3]);
    *(float4*)&g_part[base + 128 + tx*4] = make_float4(acc[r][4],acc[r][5],acc[r][6],acc[r][7]);
  }
}

// ---------------- K2b: reduce + gelu, store [bm][k][d] ----------------
__global__ void k_red1(){
  int g = blockIdx.x*256 + threadIdx.x;
  int bm = g>>14, r = g&16383;
  int k = r&255, d = r>>8;
  float s = 0.f;
  #pragma unroll
  for (int sp=0;sp<8;sp++)
    s += g_part[(size_t)((bm*8+sp)*64 + d)*KHn + k];
  g_out1T[(size_t)bm*16384 + k*64 + d] = gelu_f(s);
}

// ---------------- K3: bmm2, tile 64d x 128l, 8x4 micro ----------------
__global__ void __launch_bounds__(256) k_gemm2(){
  __shared__ float sm2[128*68];   // union: As 32x68 + Bs 32x132 (6400) ; Cs 128x68 (8704)
  float* As = sm2;
  float* Bs = sm2 + 32*68;
  const int bm = blockIdx.x, l0 = blockIdx.y*128;
  const int tid=threadIdx.x, tx=tid&31, ty=tid>>5;
  float acc[8][4];
  #pragma unroll
  for (int r=0;r<8;r++)
    #pragma unroll
    for (int c=0;c<4;c++) acc[r][c]=0.f;
  for (int kc=0;kc<256;kc+=32){
    #pragma unroll
    for (int i=0;i<2;i++){ int idx=i*256+tid, k=idx>>4, dq=idx&15;
      *(float4*)&As[k*68+dq*4] =
        *(const float4*)&g_out1T[(size_t)bm*16384 + (kc+k)*64 + dq*4]; }
    #pragma unroll
    for (int i=0;i<4;i++){ int idx=i*256+tid, k=idx>>5, lq=idx&31;
      *(float4*)&Bs[k*132+lq*4] =
        *(const float4*)&g_W2T[(size_t)(bm*KHn + kc+k)*Ln + l0 + lq*4]; }
    __syncthreads();
    #pragma unroll 2
    for (int k=0;k<32;k++){
      float4 a0 = *(const float4*)&As[k*68 + ty*8];
      float4 a1 = *(const float4*)&As[k*68 + ty*8 + 4];
      float4 b0 = *(const float4*)&Bs[k*132 + tx*4];
      float av[8] = {a0.x,a0.y,a0.z,a0.w,a1.x,a1.y,a1.z,a1.w};
      #pragma unroll
      for (int r=0;r<8;r++){
        acc[r][0]+=av[r]*b0.x; acc[r][1]+=av[r]*b0.y;
        acc[r][2]+=av[r]*b0.z; acc[r][3]+=av[r]*b0.w;
      }
    }
    __syncthreads();
  }
  // stage transposed: Cs[l][d]
  float* Cs = sm2;
  __syncthreads();
  #pragma unroll
  for (int r=0;r<8;r++)
    #pragma unroll
    for (int c=0;c<4;c++)
      Cs[(tx*4+c)*68 + ty*8+r] = acc[r][c];
  __syncthreads();
  const int b = bm>>3, m = bm&7;
  #pragma unroll
  for (int i=0;i<8;i++){ int idx=i*256+tid, l=idx>>4, dq=idx&15;
    *(float4*)&g_mixpre[(size_t)(b*Ln + l0+l)*Dn + m*64 + dq*4] =
      *(const float4*)&Cs[l*68+dq*4]; }
}

// ---------------- block reduce (128 thr) ----------------
__device__ __forceinline__ float blkSum128(float v){
  __shared__ float red[4];
  #pragma unroll
  for (int o=16;o>0;o>>=1) v += __shfl_down_sync(0xffffffffu, v, o);
  if ((threadIdx.x & 31) == 0) red[threadIdx.x>>5] = v;
  __syncthreads();
  float s = red[0]+red[1]+red[2]+red[3];
  __syncthreads();
  return s;
}

// ---------------- K4: mix = LN(mixpre); ln1 = LN(mix) ----------------
__global__ void __launch_bounds__(128) k_lnmix(
    const float* __restrict__ gm, const float* __restrict__ bb0,
    const float* __restrict__ g1, const float* __restrict__ b1){
  const int t = blockIdx.x, tid = threadIdx.x;
  float v[4];
  #pragma unroll
  for (int i=0;i<4;i++) v[i] = g_mixpre[(size_t)t*Dn + tid + i*128];
  float mean = blkSum128(v[0]+v[1]+v[2]+v[3]) * (1.f/512.f);
  float q = 0.f;
  #pragma unroll
  for (int i=0;i<4;i++){ float d=v[i]-mean; q += d*d; }
  float inv = rsqrtf(blkSum128(q)*(1.f/512.f) + 1e-5f);
  float mv[4];
  #pragma unroll
  for (int i=0;i<4;i++){
    int c = tid + i*128;
    mv[i] = (v[i]-mean)*inv*gm[c] + bb0[c];
    g_mix[(size_t)t*Dn + c] = mv[i];
  }
  float mean2 = blkSum128(mv[0]+mv[1]+mv[2]+mv[3]) * (1.f/512.f);
  float q2 = 0.f;
  #pragma unroll
  for (int i=0;i<4;i++){ float d=mv[i]-mean2; q2 += d*d; }
  float inv2 = rsqrtf(blkSum128(q2)*(1.f/512.f) + 1e-5f);
  #pragma unroll
  for (int i=0;i<4;i++){
    int c = tid + i*128;
    g_ln1[(size_t)t*Dn + c] = (mv[i]-mean2)*inv2*g1[c] + b1[c];
  }
}

// ---------------- K5: bneck 1x1 + GLU, tile 64t x 128e, 8x4 micro ----------------
__global__ void __launch_bounds__(256) k_bneck(
    const float* __restrict__ bw, const float* __restrict__ bb){
  __shared__ float smm[64*132];   // union: As 32x68 + Bs 32x132 (6400) ; ys 64x132 (8448)
  float* As = smm;
  float* Bs = smm + 32*68;
  const int t0 = blockIdx.x*64, e0 = blockIdx.y*64;
  const int tid = threadIdx.x, tx = tid&31, ty = tid>>5;
  float acc[8][4];
  #pragma unroll
  for (int r=0;r<8;r++)
    #pragma unroll
    for (int c=0;c<4;c++) acc[r][c]=0.f;
  for (int kc=0;kc<512;kc+=32){
    #pragma unroll
    for (int i=0;i<2;i++){ int idx=i*256+tid, tok=idx>>3, kq=idx&7;
      float4 v = *(const float4*)&g_ln1[(size_t)(t0+tok)*Dn + kc + kq*4];
      As[(kq*4+0)*68+tok]=v.x; As[(kq*4+1)*68+tok]=v.y;
      As[(kq*4+2)*68+tok]=v.z; As[(kq*4+3)*68+tok]=v.w; }
    #pragma unroll
    for (int i=0;i<4;i++){ int idx=i*256+tid, e=idx>>3, kq=idx&7;
      int er = (e<64) ? (e0+e) : (512 + e0 + (e-64));
      float4 v = *(const float4*)&bw[(size_t)er*Dn + kc + kq*4];
      Bs[(kq*4+0)*132+e]=v.x; Bs[(kq*4+1)*132+e]=v.y;
      Bs[(kq*4+2)*132+e]=v.z; Bs[(kq*4+3)*132+e]=v.w; }
    __syncthreads();
    #pragma unroll 2
    for (int k=0;k<32;k++){
      float4 a0 = *(const float4*)&As[k*68 + ty*8];
      float4 a1 = *(const float4*)&As[k*68 + ty*8 + 4];
      float4 b0 = *(const float4*)&Bs[k*132 + tx*4];
      float av[8] = {a0.x,a0.y,a0.z,a0.w,a1.x,a1.y,a1.z,a1.w};
      #pragma unroll
      for (int r=0;r<8;r++){
        acc[r][0]+=av[r]*b0.x; acc[r][1]+=av[r]*b0.y;
        acc[r][2]+=av[r]*b0.z; acc[r][3]+=av[r]*b0.w;
      }
    }
    __syncthreads();
  }
  float* ys = smm;
  __syncthreads();
  #pragma unroll
  for (int r=0;r<8;r++)
    #pragma unroll
    for (int c=0;c<4;c++)
      ys[(ty*8+r)*132 + tx*4+c] = acc[r][c];
  __syncthreads();
  #pragma unroll
  for (int i=0;i<4;i++){ int idx=i*256+tid, t=idx>>4, jq=idx&15;
    int j = jq*4;
    float4 ya = *(const float4*)&ys[t*132 + j];
    float4 yb = *(const float4*)&ys[t*132 + 64 + j];
    float4 ba = *(const float4*)&bb[e0 + j];
    float4 bbv= *(const float4*)&bb[512 + e0 + j];
    float4 o;
    float va;
    va = ya.x + ba.x; o.x = va * (1.f/(1.f+expf(-(yb.x+bbv.x))));
    va = ya.y + ba.y; o.y = va * (1.f/(1.f+expf(-(yb.y+bbv.y))));
    va = ya.z + ba.z; o.z = va * (1.f/(1.f+expf(-(yb.z+bbv.z))));
    va = ya.w + ba.w; o.w = va * (1.f/(1.f+expf(-(yb.w+bbv.w))));
    *(float4*)&g_glu[(size_t)(t0+t)*Dn + e0 + j] = o;
  }
}

// ---------------- K6: depthwise conv ----------------
__global__ void __launch_bounds__(256) k_dwconv(
    const float* __restrict__ dww, const float* __restrict__ dwb){
  __shared__ float gs[94*64];
  const int b = blockIdx.z, c0 = blockIdx.y*64, l0 = blockIdx.x*64;
  const int tid = threadIdx.x, c = tid&63, lw = tid>>6;
  float w[31];
  #pragma unroll
  for (int j=0;j<31;j++) w[j] = dww[(c0+c)*31 + j];
  for (int i = tid; i < 94*64; i += 256){
    int row = i>>6, cc = i&63;
    int l = l0 - 15 + row;
    gs[i] = (l>=0 && l<Ln) ? g_glu[(size_t)(b*Ln + l)*Dn + c0+cc] : 0.f;
  }
  __syncthreads();
  float bv = dwb[c0+c];
  for (int lo=0; lo<16; lo++){
    int l = lo*4 + lw;
    float acc = bv;
    #pragma unroll
    for (int j=0;j<31;j++) acc += gs[(l+j)*64 + c] * w[j];
    g_dw[(size_t)(b*Ln + l0+l)*Dn + c0+c] = acc;
  }
}

// ---------------- K7: act = gelu(LN(dw)) ----------------
__global__ void __launch_bounds__(128) k_ln2gelu(
    const float* __restrict__ g2, const float* __restrict__ b2){
  const int t = blockIdx.x, tid = threadIdx.x;
  float v[4];
  #pragma unroll
  for (int i=0;i<4;i++) v[i] = g_dw[(size_t)t*Dn + tid + i*128];
  float mean = blkSum128(v[0]+v[1]+v[2]+v[3]) * (1.f/512.f);
  float q = 0.f;
  #pragma unroll
  for (int i=0;i<4;i++){ float d=v[i]-mean; q += d*d; }
  float inv = rsqrtf(blkSum128(q)*(1.f/512.f) + 1e-5f);
  #pragma unroll
  for (int i=0;i<4;i++){
    int c = tid + i*128;
    g_act[(size_t)t*Dn + c] = gelu_f((v[i]-mean)*inv*g2[c] + b2[c]);
  }
}

// ---------------- K8: final linear + residual, tile 64t x 128d, 8x4 micro ----------------
__global__ void __launch_bounds__(256) k_lin(
    const float* __restrict__ lw, const float* __restrict__ lb,
    float* __restrict__ out){
  __shared__ float As[32*68];
  __shared__ float Bs[32*132];
  const int t0 = blockIdx.x*64, d0 = blockIdx.y*128;
  const int tid = threadIdx.x, tx = tid&31, ty = tid>>5;
  float acc[8][4];
  #pragma unroll
  for (int r=0;r<8;r++)
    #pragma unroll
    for (int c=0;c<4;c++) acc[r][c]=0.f;
  for (int kc=0;kc<512;kc+=32){
    #pragma unroll
    for (int i=0;i<2;i++){ int idx=i*256+tid, tok=idx>>3, kq=idx&7;
      float4 v = *(const float4*)&g_act[(size_t)(t0+tok)*Dn + kc + kq*4];
      As[(kq*4+0)*68+tok]=v.x; As[(kq*4+1)*68+tok]=v.y;
      As[(kq*4+2)*68+tok]=v.z; As[(kq*4+3)*68+tok]=v.w; }
    #pragma unroll
    for (int i=0;i<4;i++){ int idx=i*256+tid, e=idx>>3, kq=idx&7;
      float4 v = *(const float4*)&lw[(size_t)(d0+e)*Dn + kc + kq*4];
      Bs[(kq*4+0)*132+e]=v.x; Bs[(kq*4+1)*132+e]=v.y;
      Bs[(kq*4+2)*132+e]=v.z; Bs[(kq*4+3)*132+e]=v.w; }
    __syncthreads();
    #pragma unroll 2
    for (int k=0;k<32;k++){
      float4 a0 = *(const float4*)&As[k*68 + ty*8];
      float4 a1 = *(const float4*)&As[k*68 + ty*8 + 4];
      float4 b0 = *(const float4*)&Bs[k*132 + tx*4];
      float av[8] = {a0.x,a0.y,a0.z,a0.w,a1.x,a1.y,a1.z,a1.w};
      #pragma unroll
      for (int r=0;r<8;r++){
        acc[r][0]+=av[r]*b0.x; acc[r][1]+=av[r]*b0.y;
        acc[r][2]+=av[r]*b0.z; acc[r][3]+=av[r]*b0.w;
      }
    }
    __syncthreads();
  }
  float4 lb4 = *(const float4*)&lb[d0 + tx*4];
  #pragma unroll
  for (int r=0;r<8;r++){
    size_t o = (size_t)(t0 + ty*8+r)*Dn + d0 + tx*4;
    float4 mv = *(const float4*)&g_mix[o];
    float4 ov;
    ov.x = mv.x + acc[r][0] + lb4.x;
    ov.y = mv.y + acc[r][1] + lb4.y;
    ov.z = mv.z + acc[r][2] + lb4.z;
    ov.w = mv.w + acc[r][3] + lb4.w;
    *(float4*)&out[o] = ov;
  }
}

// ---------------- launch ----------------
extern "C" void kernel_launch(void* const* d_in, const int* in_sizes, int n_in,
                              void* d_out, int out_size) {
  const float* x      = (const float*)d_in[0];
  const float* w1f1w  = (const float*)d_in[1];
  const float* w1f1b  = (const float*)d_in[2];
  const float* w1f2w  = (const float*)d_in[3];
  const float* w1f2b  = (const float*)d_in[4];
  const float* w2f1w  = (const float*)d_in[5];
  const float* w2f1b  = (const float*)d_in[6];
  const float* w2f2w  = (const float*)d_in[7];
  const float* w2f2b  = (const float*)d_in[8];
  const float* lnmg   = (const float*)d_in[9];
  const float* lnmb   = (const float*)d_in[10];
  const float* ln1g   = (const float*)d_in[11];
  const float* ln1b   = (const float*)d_in[12];
  const float* bw     = (const float*)d_in[13];
  const float* bb     = (const float*)d_in[14];
  const float* dww    = (const float*)d_in[15];
  const float* dwb    = (const float*)d_in[16];
  const float* ln2g   = (const float*)d_in[17];
  const float* ln2b   = (const float*)d_in[18];
  const float* lw     = (const float*)d_in[19];
  const float* lb     = (const float*)d_in[20];
  float* out = (float*)d_out;

  const int pmlp_smem = 21760 * 4;   // 87040 B
  cudaFuncSetAttribute(k_pmlp, cudaFuncAttributeMaxDynamicSharedMemorySize, pmlp_smem);

  k_pmlp<<<dim3(Tn/64, Mn), 256, pmlp_smem>>>(x, w1f1w, w1f1b, w1f2w, w1f2b,
                                              w2f1w, w2f1b, w2f2w, w2f2b);
  k_gemm1<<<dim3(BMn, 8), 256>>>(x);
  k_red1<<<4096, 256>>>();
  k_gemm2<<<dim3(BMn, 16), 256>>>();
  k_lnmix<<<Tn, 128>>>(lnmg, lnmb, ln1g, ln1b);
  k_bneck<<<dim3(Tn/64, 8), 256>>>(bw, bb);
  k_dwconv<<<dim3(32, 8, 8), 256>>>(dww, dwb);
  k_ln2gelu<<<Tn, 128>>>(ln2g, ln2b);
  k_lin<<<dim3(Tn/64, 4), 256>>>(lw, lb, out);
}

// round 7
// speedup vs baseline: 1.9484x; 1.3249x over previous
#include <cuda_runtime.h>
#include <cuda_fp16.h>
#include <mma.h>
#include <math.h>
#include <stdint.h>

using namespace nvcuda;

#define Bn 8
#define Ln 2048
#define Dn 512
#define Mn 8
#define KHn 256
#define BMn 64
#define Tn (Bn*Ln)

// ---------------- scratch ----------------
__device__ float g_W1  [(size_t)BMn*Ln*KHn];    // [bm][l][k]
__device__ float g_W2T [(size_t)BMn*KHn*Ln];    // [bm][k][l]
__device__ float g_part[(size_t)BMn*8*64*KHn];  // [bm*8+sp][d][k]
__device__ float g_out1T[(size_t)BMn*KHn*64];   // [bm][k][d]
__device__ float g_mixpre[(size_t)Tn*Dn];
__device__ float g_mix [(size_t)Tn*Dn];
__device__ float g_glu [(size_t)Tn*Dn];
__device__ float g_dw  [(size_t)Tn*Dn];
__device__ __half g_ln1h[(size_t)Tn*Dn];
__device__ __half g_acth[(size_t)Tn*Dn];
__device__ __half g_bwh [(size_t)1024*512];
__device__ __half g_lwh [(size_t)512*512];

__device__ __forceinline__ float gelu_f(float v){
  return 0.5f*v*(1.0f+erff(v*0.70710678118654752f));
}

// ---------------- K1: fused hypernet MLPs ----------------
__global__ void __launch_bounds__(256) k_pmlp(
    const float* __restrict__ x,
    const float* __restrict__ w1f1w, const float* __restrict__ w1f1b,
    const float* __restrict__ w1f2w, const float* __restrict__ w1f2b,
    const float* __restrict__ w2f1w, const float* __restrict__ w2f1b,
    const float* __restrict__ w2f2w, const float* __restrict__ w2f2b)
{
  extern __shared__ float sm[];
  float* xs = sm;             // 64 x 68 (reused as ys in phase B)
  float* ws = sm + 4352;      // 2 x 64 x 68
  float* hs = ws + 8704;      // 2 x 64 x 68
  const int m = blockIdx.y, t0 = blockIdx.x*64;
  const int b = t0 >> 11, l0 = t0 & (Ln-1), bm = b*Mn + m;
  const int tid = threadIdx.x;
  const float c0 = -9.210340371976184f / 512.0f;

  #pragma unroll
  for (int i = 0; i < 16; i++) {
    int idx = i*256 + tid, tok = idx>>6, f = idx&63;
    int ch = m*64 + f, l = l0 + tok;
    float ang = (float)l * expf((float)(ch & ~1) * c0);
    float pe  = (ch & 1) ? cosf(ang) : sinf(ang);
    xs[tok*68+f] = x[(size_t)(b*Ln + l)*Dn + ch] + pe;
  }
  #pragma unroll
  for (int i = 0; i < 32; i++) {
    int idx = i*256 + tid, net = idx>>12, r = idx&4095;
    int hid = r>>6, f = r&63;
    const float* w = net ? w2f1w : w1f1w;
    ws[net*4352 + hid*68 + f] = w[m*4096 + hid*64 + f];
  }
  __syncthreads();
  #pragma unroll
  for (int i = 0; i < 8; i++) {
    int idx = i*256 + tid;
    int net = idx>>10, hp = (idx>>5)&31, tp = idx&31;
    int h0 = hp*2, ta = tp*2;
    const float* bp = net ? w2f1b : w1f1b;
    float b0 = bp[m*64+h0], b1 = bp[m*64+h0+1];
    float a00=b0, a01=b0, a10=b1, a11=b1;
    const float4* w0r=(const float4*)(ws + net*4352 + h0*68);
    const float4* w1r=(const float4*)(ws + net*4352 + (h0+1)*68);
    const float4* xa =(const float4*)(xs + ta*68);
    const float4* xb =(const float4*)(xs + (ta+1)*68);
    #pragma unroll
    for (int q = 0; q < 16; q++) {
      float4 w0=w0r[q], w1=w1r[q], va=xa[q], vb=xb[q];
      a00 += va.x*w0.x+va.y*w0.y+va.z*w0.z+va.w*w0.w;
      a01 += vb.x*w0.x+vb.y*w0.y+vb.z*w0.z+vb.w*w0.w;
      a10 += va.x*w1.x+va.y*w1.y+va.z*w1.z+va.w*w1.w;
      a11 += vb.x*w1.x+vb.y*w1.y+vb.z*w1.z+vb.w*w1.w;
    }
    hs[net*4352 + ta*68     + h0  ] = gelu_f(a00);
    hs[net*4352 + (ta+1)*68 + h0  ] = gelu_f(a01);
    hs[net*4352 + ta*68     + h0+1] = gelu_f(a10);
    hs[net*4352 + (ta+1)*68 + h0+1] = gelu_f(a11);
  }
  __syncthreads();
  float* ys = xs;
  for (int kc = 0; kc < 4; kc++) {
    #pragma unroll
    for (int i = 0; i < 32; i++) {
      int idx = i*256 + tid, net = idx>>12, r = idx&4095;
      int kk = r>>6, h = r&63;
      const float* w = net ? w2f2w : w1f2w;
      ws[net*4352 + kk*68 + h] = w[m*16384 + (kc*64+kk)*64 + h];
    }
    __syncthreads();
    for (int net = 0; net < 2; net++) {
      #pragma unroll
      for (int i = 0; i < 4; i++) {
        int idx = i*256 + tid;
        int kp = idx>>5, tp = idx&31;
        int k0 = kp*2, ta = tp*2;
        const float* bp = net ? w2f2b : w1f2b;
        float b0 = bp[m*256 + kc*64 + k0], b1 = bp[m*256 + kc*64 + k0+1];
        float a00=b0, a01=b0, a10=b1, a11=b1;
        const float4* w0r=(const float4*)(ws + net*4352 + k0*68);
        const float4* w1r=(const float4*)(ws + net*4352 + (k0+1)*68);
        const float4* ha =(const float4*)(hs + net*4352 + ta*68);
        const float4* hb =(const float4*)(hs + net*4352 + (ta+1)*68);
        #pragma unroll
        for (int q = 0; q < 16; q++) {
          float4 w0=w0r[q], w1=w1r[q], va=ha[q], vb=hb[q];
          a00 += va.x*w0.x+va.y*w0.y+va.z*w0.z+va.w*w0.w;
          a01 += vb.x*w0.x+vb.y*w0.y+vb.z*w0.z+vb.w*w0.w;
          a10 += va.x*w1.x+va.y*w1.y+va.z*w1.z+va.w*w1.w;
          a11 += vb.x*w1.x+vb.y*w1.y+vb.z*w1.z+vb.w*w1.w;
        }
        ys[ta*68     + k0  ] = a00;
        ys[(ta+1)*68 + k0  ] = a01;
        ys[ta*68     + k0+1] = a10;
        ys[(ta+1)*68 + k0+1] = a11;
      }
      __syncthreads();
      if (net == 0) {
        #pragma unroll
        for (int i = 0; i < 16; i++) {
          int idx = i*256 + tid, kk = idx&63, tok = idx>>6;
          g_W1[(size_t)(bm*Ln + l0+tok)*KHn + kc*64+kk] = ys[tok*68+kk];
        }
      } else {
        #pragma unroll
        for (int i = 0; i < 16; i++) {
          int idx = i*256 + tid, tok = idx&63, kk = idx>>6;
          g_W2T[(size_t)(bm*KHn + kc*64+kk)*Ln + l0 + tok] = ys[tok*68+kk];
        }
      }
      __syncthreads();
    }
  }
}

// ---------------- K2: bmm1 split-K ----------------
__global__ void __launch_bounds__(256) k_gemm1(const float* __restrict__ x){
  __shared__ float As[32*68];
  __shared__ float Bs[32*260];
  const int bm = blockIdx.x, sp = blockIdx.y;
  const int b = bm>>3, m = bm&7;
  const int tid = threadIdx.x, tx = tid&31, ty = tid>>5;
  float acc[8][8];
  #pragma unroll
  for (int r=0;r<8;r++)
    #pragma unroll
    for (int c=0;c<8;c++) acc[r][c]=0.f;
  const int lbase = sp*256;
  for (int lc = 0; lc < 256; lc += 32) {
    #pragma unroll
    for (int i=0;i<2;i++){ int idx=i*256+tid, l=idx>>4, dq=idx&15;
      *(float4*)&As[l*68+dq*4] =
        *(const float4*)&x[(size_t)(b*Ln + lbase+lc+l)*Dn + m*64 + dq*4]; }
    #pragma unroll
    for (int i=0;i<8;i++){ int idx=i*256+tid, l=idx>>6, kq=idx&63;
      *(float4*)&Bs[l*260+kq*4] =
        *(const float4*)&g_W1[(size_t)(bm*Ln + lbase+lc+l)*KHn + kq*4]; }
    __syncthreads();
    #pragma unroll 2
    for (int l=0;l<32;l++){
      float4 a0 = *(const float4*)&As[l*68 + ty*8];
      float4 a1 = *(const float4*)&As[l*68 + ty*8 + 4];
      float4 b0 = *(const float4*)&Bs[l*260 + tx*4];
      float4 b1 = *(const float4*)&Bs[l*260 + 128 + tx*4];
      float av[8] = {a0.x,a0.y,a0.z,a0.w,a1.x,a1.y,a1.z,a1.w};
      float bv[8] = {b0.x,b0.y,b0.z,b0.w,b1.x,b1.y,b1.z,b1.w};
      #pragma unroll
      for (int r=0;r<8;r++)
        #pragma unroll
        for (int c=0;c<8;c++) acc[r][c] += av[r]*bv[c];
    }
    __syncthreads();
  }
  #pragma unroll
  for (int r=0;r<8;r++){
    size_t base = (size_t)((bm*8+sp)*64 + ty*8+r)*KHn;
    *(float4*)&g_part[base + tx*4]       = make_float4(acc[r][0],acc[r][1],acc[r][2],acc[r][3]);
    *(float4*)&g_part[base + 128 + tx*4] = make_float4(acc[r][4],acc[r][5],acc[r][6],acc[r][7]);
  }
}

// ---------------- K2b: reduce + gelu ----------------
__global__ void k_red1(){
  int g = blockIdx.x*256 + threadIdx.x;
  int bm = g>>14, r = g&16383;
  int k = r&255, d = r>>8;
  float s = 0.f;
  #pragma unroll
  for (int sp=0;sp<8;sp++)
    s += g_part[(size_t)((bm*8+sp)*64 + d)*KHn + k];
  g_out1T[(size_t)bm*16384 + k*64 + d] = gelu_f(s);
}

// ---------------- K3: bmm2 ----------------
__global__ void __launch_bounds__(256) k_gemm2(){
  __shared__ float sm2[128*68];
  float* As = sm2;
  float* Bs = sm2 + 32*68;
  const int bm = blockIdx.x, l0 = blockIdx.y*128;
  const int tid=threadIdx.x, tx=tid&31, ty=tid>>5;
  float acc[8][4];
  #pragma unroll
  for (int r=0;r<8;r++)
    #pragma unroll
    for (int c=0;c<4;c++) acc[r][c]=0.f;
  for (int kc=0;kc<256;kc+=32){
    #pragma unroll
    for (int i=0;i<2;i++){ int idx=i*256+tid, k=idx>>4, dq=idx&15;
      *(float4*)&As[k*68+dq*4] =
        *(const float4*)&g_out1T[(size_t)bm*16384 + (kc+k)*64 + dq*4]; }
    #pragma unroll
    for (int i=0;i<4;i++){ int idx=i*256+tid, k=idx>>5, lq=idx&31;
      *(float4*)&Bs[k*132+lq*4] =
        *(const float4*)&g_W2T[(size_t)(bm*KHn + kc+k)*Ln + l0 + lq*4]; }
    __syncthreads();
    #pragma unroll 2
    for (int k=0;k<32;k++){
      float4 a0 = *(const float4*)&As[k*68 + ty*8];
      float4 a1 = *(const float4*)&As[k*68 + ty*8 + 4];
      float4 b0 = *(const float4*)&Bs[k*132 + tx*4];
      float av[8] = {a0.x,a0.y,a0.z,a0.w,a1.x,a1.y,a1.z,a1.w};
      #pragma unroll
      for (int r=0;r<8;r++){
        acc[r][0]+=av[r]*b0.x; acc[r][1]+=av[r]*b0.y;
        acc[r][2]+=av[r]*b0.z; acc[r][3]+=av[r]*b0.w;
      }
    }
    __syncthreads();
  }
  float* Cs = sm2;
  __syncthreads();
  #pragma unroll
  for (int r=0;r<8;r++)
    #pragma unroll
    for (int c=0;c<4;c++)
      Cs[(tx*4+c)*68 + ty*8+r] = acc[r][c];
  __syncthreads();
  const int b = bm>>3, m = bm&7;
  #pragma unroll
  for (int i=0;i<8;i++){ int idx=i*256+tid, l=idx>>4, dq=idx&15;
    *(float4*)&g_mixpre[(size_t)(b*Ln + l0+l)*Dn + m*64 + dq*4] =
      *(const float4*)&Cs[l*68+dq*4]; }
}

// ---------------- block reduce (128 thr) ----------------
__device__ __forceinline__ float blkSum128(float v){
  __shared__ float red[4];
  #pragma unroll
  for (int o=16;o>0;o>>=1) v += __shfl_down_sync(0xffffffffu, v, o);
  if ((threadIdx.x & 31) == 0) red[threadIdx.x>>5] = v;
  __syncthreads();
  float s = red[0]+red[1]+red[2]+red[3];
  __syncthreads();
  return s;
}

// ---------------- K4: mix = LN(mixpre); ln1h = fp16(LN(mix)) ----------------
__global__ void __launch_bounds__(128) k_lnmix(
    const float* __restrict__ gm, const float* __restrict__ bb0,
    const float* __restrict__ g1, const float* __restrict__ b1){
  const int t = blockIdx.x, tid = threadIdx.x;
  float v[4];
  #pragma unroll
  for (int i=0;i<4;i++) v[i] = g_mixpre[(size_t)t*Dn + tid + i*128];
  float mean = blkSum128(v[0]+v[1]+v[2]+v[3]) * (1.f/512.f);
  float q = 0.f;
  #pragma unroll
  for (int i=0;i<4;i++){ float d=v[i]-mean; q += d*d; }
  float inv = rsqrtf(blkSum128(q)*(1.f/512.f) + 1e-5f);
  float mv[4];
  #pragma unroll
  for (int i=0;i<4;i++){
    int c = tid + i*128;
    mv[i] = (v[i]-mean)*inv*gm[c] + bb0[c];
    g_mix[(size_t)t*Dn + c] = mv[i];
  }
  float mean2 = blkSum128(mv[0]+mv[1]+mv[2]+mv[3]) * (1.f/512.f);
  float q2 = 0.f;
  #pragma unroll
  for (int i=0;i<4;i++){ float d=mv[i]-mean2; q2 += d*d; }
  float inv2 = rsqrtf(blkSum128(q2)*(1.f/512.f) + 1e-5f);
  #pragma unroll
  for (int i=0;i<4;i++){
    int c = tid + i*128;
    g_ln1h[(size_t)t*Dn + c] = __float2half_rn((mv[i]-mean2)*inv2*g1[c] + b1[c]);
  }
}

// ---------------- weight fp16 conversion ----------------
__global__ void k_convw(const float* __restrict__ bw, const float* __restrict__ lw){
  int i = blockIdx.x*256 + threadIdx.x;
  if (i < 1024*512) g_bwh[i] = __float2half_rn(bw[i]);
  else              g_lwh[i - 1024*512] = __float2half_rn(lw[i - 1024*512]);
}

// ---------------- K5/K8: wmma fp16 GEMM (mode 0 = bneck+GLU, 1 = lin+residual) ----------------
// tile: 128 tokens x 128 cols; 8 warps (4 m x 2 n); warp tile 32 x 64
// smem union: A/B stage 2x128x40 halves (20480 B) ; C stage 128x132 f32 (67584 B)
#define HG_SMEM 67584

__global__ void __launch_bounds__(256) k_hgemm(int mode,
    const float* __restrict__ bias, float* __restrict__ extout){
  extern __shared__ char wsmraw[];
  __half* Ash = (__half*)wsmraw;                 // 128 x 40
  __half* Bsh = (__half*)(wsmraw + 128*40*2);    // 128 x 40
  float*  Cs  = (float*)wsmraw;                  // 128 x 132
  const int tid = threadIdx.x, wid = tid>>5;
  const int wm = wid & 3, wn = wid >> 2;
  const int t0 = blockIdx.x*128;
  const int e0 = blockIdx.y * (mode ? 128 : 64);
  const __half* Xh = mode ? g_acth : g_ln1h;
  const __half* Wh = mode ? g_lwh  : g_bwh;

  wmma::fragment<wmma::accumulator,16,16,16,float> cf[2][4];
  #pragma unroll
  for (int r=0;r<2;r++)
    #pragma unroll
    for (int c=0;c<4;c++) wmma::fill_fragment(cf[r][c], 0.0f);

  for (int kc = 0; kc < 512; kc += 32) {
    #pragma unroll
    for (int i=0;i<2;i++){ int idx=i*256+tid, r=idx>>2, u=idx&3;
      *(uint4*)&Ash[r*40 + u*8] = *(const uint4*)&Xh[(size_t)(t0+r)*512 + kc + u*8]; }
    #pragma unroll
    for (int i=0;i<2;i++){ int idx=i*256+tid, r=idx>>2, u=idx&3;
      int er = mode ? (e0 + r) : ((r < 64) ? (e0 + r) : (512 + e0 + (r - 64)));
      *(uint4*)&Bsh[r*40 + u*8] = *(const uint4*)&Wh[(size_t)er*512 + kc + u*8]; }
    __syncthreads();
    #pragma unroll
    for (int ks = 0; ks < 32; ks += 16) {
      wmma::fragment<wmma::matrix_a,16,16,16,__half,wmma::row_major> af[2];
      wmma::fragment<wmma::matrix_b,16,16,16,__half,wmma::col_major> bf[4];
      wmma::load_matrix_sync(af[0], &Ash[(wm*32    )*40 + ks], 40);
      wmma::load_matrix_sync(af[1], &Ash[(wm*32 + 16)*40 + ks], 40);
      #pragma unroll
      for (int c=0;c<4;c++)
        wmma::load_matrix_sync(bf[c], &Bsh[(wn*64 + c*16)*40 + ks], 40);
      #pragma unroll
      for (int r=0;r<2;r++)
        #pragma unroll
        for (int c=0;c<4;c++)
          wmma::mma_sync(cf[r][c], af[r], bf[c], cf[r][c]);
    }
    __syncthreads();
  }
  #pragma unroll
  for (int r=0;r<2;r++)
    #pragma unroll
    for (int c=0;c<4;c++)
      wmma::store_matrix_sync(&Cs[(wm*32 + r*16)*132 + wn*64 + c*16], cf[r][c],
                              132, wmma::mem_row_major);
  __syncthreads();

  if (mode == 0) {
    // 128 rows x 64 glu outputs (cols 0..63 = a, 64..127 = b)
    #pragma unroll
    for (int i=0;i<8;i++){
      int idx = i*256 + tid;
      int row = idx >> 4, jq = idx & 15;
      int j = jq*4;
      float4 ya = *(const float4*)&Cs[row*132 + j];
      float4 yb = *(const float4*)&Cs[row*132 + 64 + j];
      float4 ba = *(const float4*)&bias[e0 + j];
      float4 bbv= *(const float4*)&bias[512 + e0 + j];
      float4 o;
      o.x = (ya.x + ba.x) * (1.f/(1.f+expf(-(yb.x+bbv.x))));
      o.y = (ya.y + ba.y) * (1.f/(1.f+expf(-(yb.y+bbv.y))));
      o.z = (ya.z + ba.z) * (1.f/(1.f+expf(-(yb.z+bbv.z))));
      o.w = (ya.w + ba.w) * (1.f/(1.f+expf(-(yb.w+bbv.w))));
      *(float4*)&g_glu[(size_t)(t0+row)*512 + e0 + j] = o;
    }
  } else {
    // 128 rows x 128 cols with residual
    #pragma unroll
    for (int i=0;i<16;i++){
      int idx = i*256 + tid;
      int row = idx >> 5, jq = idx & 31;
      int j = jq*4;
      size_t o = (size_t)(t0+row)*512 + e0 + j;
      float4 cv = *(const float4*)&Cs[row*132 + j];
      float4 mv = *(const float4*)&g_mix[o];
      float4 lb4= *(const float4*)&bias[e0 + j];
      float4 ov;
      ov.x = mv.x + cv.x + lb4.x;
      ov.y = mv.y + cv.y + lb4.y;
      ov.z = mv.z + cv.z + lb4.z;
      ov.w = mv.w + cv.w + lb4.w;
      *(float4*)&extout[o] = ov;
    }
  }
}

// ---------------- K6: depthwise conv ----------------
__global__ void __launch_bounds__(256) k_dwconv(
    const float* __restrict__ dww, const float* __restrict__ dwb){
  __shared__ float gs[94*64];
  const int b = blockIdx.z, c0 = blockIdx.y*64, l0 = blockIdx.x*64;
  const int tid = threadIdx.x, c = tid&63, lw = tid>>6;
  float w[31];
  #pragma unroll
  for (int j=0;j<31;j++) w[j] = dww[(c0+c)*31 + j];
  for (int i = tid; i < 94*64; i += 256){
    int row = i>>6, cc = i&63;
    int l = l0 - 15 + row;
    gs[i] = (l>=0 && l<Ln) ? g_glu[(size_t)(b*Ln + l)*Dn + c0+cc] : 0.f;
  }
  __syncthreads();
  float bv = dwb[c0+c];
  for (int lo=0; lo<16; lo++){
    int l = lo*4 + lw;
    float acc = bv;
    #pragma unroll
    for (int j=0;j<31;j++) acc += gs[(l+j)*64 + c] * w[j];
    g_dw[(size_t)(b*Ln + l0+l)*Dn + c0+c] = acc;
  }
}

// ---------------- K7: acth = fp16(gelu(LN(dw))) ----------------
__global__ void __launch_bounds__(128) k_ln2gelu(
    const float* __restrict__ g2, const float* __restrict__ b2){
  const int t = blockIdx.x, tid = threadIdx.x;
  float v[4];
  #pragma unroll
  for (int i=0;i<4;i++) v[i] = g_dw[(size_t)t*Dn + tid + i*128];
  float mean = blkSum128(v[0]+v[1]+v[2]+v[3]) * (1.f/512.f);
  float q = 0.f;
  #pragma unroll
  for (int i=0;i<4;i++){ float d=v[i]-mean; q += d*d; }
  float inv = rsqrtf(blkSum128(q)*(1.f/512.f) + 1e-5f);
  #pragma unroll
  for (int i=0;i<4;i++){
    int c = tid + i*128;
    g_acth[(size_t)t*Dn + c] = __float2half_rn(gelu_f((v[i]-mean)*inv*g2[c] + b2[c]));
  }
}

// ---------------- launch ----------------
extern "C" void kernel_launch(void* const* d_in, const int* in_sizes, int n_in,
                              void* d_out, int out_size) {
  const float* x      = (const float*)d_in[0];
  const float* w1f1w  = (const float*)d_in[1];
  const float* w1f1b  = (const float*)d_in[2];
  const float* w1f2w  = (const float*)d_in[3];
  const float* w1f2b  = (const float*)d_in[4];
  const float* w2f1w  = (const float*)d_in[5];
  const float* w2f1b  = (const float*)d_in[6];
  const float* w2f2w  = (const float*)d_in[7];
  const float* w2f2b  = (const float*)d_in[8];
  const float* lnmg   = (const float*)d_in[9];
  const float* lnmb   = (const float*)d_in[10];
  const float* ln1g   = (const float*)d_in[11];
  const float* ln1b   = (const float*)d_in[12];
  const float* bw     = (const float*)d_in[13];
  const float* bb     = (const float*)d_in[14];
  const float* dww    = (const float*)d_in[15];
  const float* dwb    = (const float*)d_in[16];
  const float* ln2g   = (const float*)d_in[17];
  const float* ln2b   = (const float*)d_in[18];
  const float* lw     = (const float*)d_in[19];
  const float* lb     = (const float*)d_in[20];
  float* out = (float*)d_out;

  const int pmlp_smem = 21760 * 4;   // 87040 B
  cudaFuncSetAttribute(k_pmlp, cudaFuncAttributeMaxDynamicSharedMemorySize, pmlp_smem);
  cudaFuncSetAttribute(k_hgemm, cudaFuncAttributeMaxDynamicSharedMemorySize, HG_SMEM);

  k_convw<<<3072, 256>>>(bw, lw);
  k_pmlp<<<dim3(Tn/64, Mn), 256, pmlp_smem>>>(x, w1f1w, w1f1b, w1f2w, w1f2b,
                                              w2f1w, w2f1b, w2f2w, w2f2b);
  k_gemm1<<<dim3(BMn, 8), 256>>>(x);
  k_red1<<<4096, 256>>>();
  k_gemm2<<<dim3(BMn, 16), 256>>>();
  k_lnmix<<<Tn, 128>>>(lnmg, lnmb, ln1g, ln1b);
  k_hgemm<<<dim3(Tn/128, 8), 256, HG_SMEM>>>(0, bb, nullptr);
  k_dwconv<<<dim3(32, 8, 8), 256>>>(dww, dwb);
  k_ln2gelu<<<Tn, 128>>>(ln2g, ln2b);
  k_hgemm<<<dim3(Tn/128, 4), 256, HG_SMEM>>>(1, lb, out);
}

// round 9
// speedup vs baseline: 6.1146x; 3.1383x over previous
#include <cuda_runtime.h>
#include <cuda_fp16.h>
#include <mma.h>
#include <math.h>
#include <stdint.h>

using namespace nvcuda;

#define Bn 8
#define Ln 2048
#define Dn 512
#define Mn 8
#define KHn 256
#define BMn 64
#define Tn (Bn*Ln)

// ---------------- scratch ----------------
__device__ float  g_part[(size_t)BMn*8*64*KHn];  // [bm*8+sp][d][k] fp32 split-K partials
__device__ float  g_mixpre[(size_t)Tn*Dn];
__device__ float  g_mix [(size_t)Tn*Dn];
__device__ float  g_glu [(size_t)Tn*Dn];
__device__ float  g_dw  [(size_t)Tn*Dn];
__device__ __half g_ln1h[(size_t)Tn*Dn];
__device__ __half g_acth[(size_t)Tn*Dn];
__device__ __half g_bwh [(size_t)1024*512];
__device__ __half g_lwh [(size_t)512*512];
__device__ __half g_xh  [(size_t)Tn*Dn];
__device__ __half g_w1f1h[(size_t)Mn*64*64];
__device__ __half g_w2f1h[(size_t)Mn*64*64];
__device__ __half g_w1f2h[(size_t)Mn*256*64];
__device__ __half g_w2f2h[(size_t)Mn*256*64];
__device__ __half g_hidh[(size_t)BMn*2*Ln*64];   // [(bm*2+net)][l][64]
__device__ __half g_W1h [(size_t)BMn*Ln*256];    // [bm][l][k]
__device__ __half g_W2h [(size_t)BMn*Ln*256];    // [bm][l][k]
__device__ __half g_out1h[(size_t)BMn*256*64];   // [bm][k][d]

__device__ __forceinline__ float gelu_f(float v){
  return 0.5f*v*(1.0f+erff(v*0.70710678118654752f));
}

// ---------------- fp32 -> fp16 converters ----------------
__global__ void k_half(const float* __restrict__ s, __half* __restrict__ d, int n){
  int i = blockIdx.x*256 + threadIdx.x;
  if (i < n) d[i] = __float2half_rn(s[i]);
}
__global__ void k_convw(const float* __restrict__ bw, const float* __restrict__ lw){
  int i = blockIdx.x*256 + threadIdx.x;
  if (i < 1024*512) g_bwh[i] = __float2half_rn(bw[i]);
  else              g_lwh[i - 1024*512] = __float2half_rn(lw[i - 1024*512]);
}

// ---------------- K1a: hidden = gelu(fc1 @ (x+PE) + b), wmma ----------------
// grid (16 ltile, 64 bm), 256 thr. M=128 tok, N=128 (2 nets x 64 hid), K=64.
#define PA_SMEM (18432 + 67584)
__global__ void __launch_bounds__(256) k_pmlpA(
    const float* __restrict__ x,
    const float* __restrict__ b1f1, const float* __restrict__ b2f1){
  extern __shared__ char psm[];
  __half* Ah = (__half*)psm;             // 128 x 72
  __half* Bh = (__half*)(psm + 18432);   // 128 x 72 (n-major rows)
  float*  Cs = (float*)(psm + 18432);    // 128 x 132 (union with Bh)
  const int l0 = blockIdx.x*128;
  const int bm = blockIdx.y, b = bm>>3, m = bm&7;
  const int tid = threadIdx.x, wid = tid>>5;
  const int wm = wid&3, wn = wid>>2;
  const float c0 = -9.210340371976184f/512.0f;

  #pragma unroll 4
  for (int i=0;i<32;i++){
    int idx=i*256+tid, tok=idx>>6, f=idx&63;
    int ch = m*64+f, l = l0+tok;
    float ang = (float)l * expf((float)(ch&~1)*c0);
    float pe = (ch&1)? cosf(ang) : sinf(ang);
    Ah[tok*72+f] = __float2half_rn(x[(size_t)(b*Ln+l)*Dn+ch] + pe);
  }
  #pragma unroll
  for (int i=0;i<4;i++){
    int idx=i*256+tid, n=idx>>3, u=idx&7;
    const __half* w = (n>=64)? g_w2f1h : g_w1f1h;
    *(uint4*)&Bh[n*72+u*8] = *(const uint4*)&w[m*4096 + (n&63)*64 + u*8];
  }
  __syncthreads();

  wmma::fragment<wmma::accumulator,16,16,16,float> cf[2][4];
  #pragma unroll
  for (int r=0;r<2;r++)
    #pragma unroll
    for (int c=0;c<4;c++) wmma::fill_fragment(cf[r][c], 0.0f);
  #pragma unroll
  for (int ks=0; ks<64; ks+=16){
    wmma::fragment<wmma::matrix_a,16,16,16,__half,wmma::row_major> af[2];
    wmma::fragment<wmma::matrix_b,16,16,16,__half,wmma::col_major> bf[4];
    #pragma unroll
    for (int r=0;r<2;r++)
      wmma::load_matrix_sync(af[r], &Ah[(wm*32+r*16)*72 + ks], 72);
    #pragma unroll
    for (int c=0;c<4;c++)
      wmma::load_matrix_sync(bf[c], &Bh[(wn*64+c*16)*72 + ks], 72);
    #pragma unroll
    for (int r=0;r<2;r++)
      #pragma unroll
      for (int c=0;c<4;c++)
        wmma::mma_sync(cf[r][c], af[r], bf[c], cf[r][c]);
  }
  __syncthreads();
  #pragma unroll
  for (int r=0;r<2;r++)
    #pragma unroll
    for (int c=0;c<4;c++)
      wmma::store_matrix_sync(&Cs[(wm*32+r*16)*132 + wn*64+c*16], cf[r][c], 132,
                              wmma::mem_row_major);
  __syncthreads();
  #pragma unroll 4
  for (int i=0;i<64;i++){
    int idx=i*256+tid, tok=idx>>7, n=idx&127;
    int net=n>>6, hid=n&63;
    float bias = net? b2f1[m*64+hid] : b1f1[m*64+hid];
    float v = gelu_f(Cs[tok*132+n] + bias);
    g_hidh[((size_t)(bm*2+net)*Ln + l0+tok)*64 + hid] = __float2half_rn(v);
  }
}

// ---------------- K1b: W = fc2 @ hidden + b, wmma ----------------
// grid (16 ltile, 128 bm*net), 256 thr. M=128 tok, N=256 (2 passes of 128), K=64.
__global__ void __launch_bounds__(256) k_pmlpB(
    const float* __restrict__ b1f2, const float* __restrict__ b2f2){
  extern __shared__ char psm[];
  __half* Ah = (__half*)psm;             // 128 x 72
  __half* Bh = (__half*)(psm + 18432);   // 128 x 72
  float*  Cs = (float*)(psm + 18432);    // 128 x 132
  const int l0 = blockIdx.x*128;
  const int bmnet = blockIdx.y, bm = bmnet>>1, net = bmnet&1, m = bm&7;
  const int tid = threadIdx.x, wid = tid>>5;
  const int wm = wid&3, wn = wid>>2;
  const __half* w = net? g_w2f2h : g_w1f2h;
  const float* bias = net? b2f2 : b1f2;
  __half* dst = net? g_W2h : g_W1h;

  #pragma unroll
  for (int i=0;i<4;i++){
    int idx=i*256+tid, row=idx>>3, u=idx&7;
    *(uint4*)&Ah[row*72+u*8] =
      *(const uint4*)&g_hidh[((size_t)(bm*2+net)*Ln + l0+row)*64 + u*8];
  }
  for (int pass=0; pass<2; pass++){
    const int n0 = pass*128;
    #pragma unroll
    for (int i=0;i<4;i++){
      int idx=i*256+tid, n=idx>>3, u=idx&7;
      *(uint4*)&Bh[n*72+u*8] = *(const uint4*)&w[m*16384 + (size_t)(n0+n)*64 + u*8];
    }
    __syncthreads();
    wmma::fragment<wmma::accumulator,16,16,16,float> cf[2][4];
    #pragma unroll
    for (int r=0;r<2;r++)
      #pragma unroll
      for (int c=0;c<4;c++) wmma::fill_fragment(cf[r][c], 0.0f);
    #pragma unroll
    for (int ks=0; ks<64; ks+=16){
      wmma::fragment<wmma::matrix_a,16,16,16,__half,wmma::row_major> af[2];
      wmma::fragment<wmma::matrix_b,16,16,16,__half,wmma::col_major> bf[4];
      #pragma unroll
      for (int r=0;r<2;r++)
        wmma::load_matrix_sync(af[r], &Ah[(wm*32+r*16)*72 + ks], 72);
      #pragma unroll
      for (int c=0;c<4;c++)
        wmma::load_matrix_sync(bf[c], &Bh[(wn*64+c*16)*72 + ks], 72);
      #pragma unroll
      for (int r=0;r<2;r++)
        #pragma unroll
        for (int c=0;c<4;c++)
          wmma::mma_sync(cf[r][c], af[r], bf[c], cf[r][c]);
    }
    __syncthreads();
    #pragma unroll
    for (int r=0;r<2;r++)
      #pragma unroll
      for (int c=0;c<4;c++)
        wmma::store_matrix_sync(&Cs[(wm*32+r*16)*132 + wn*64+c*16], cf[r][c], 132,
                                wmma::mem_row_major);
    __syncthreads();
    #pragma unroll 4
    for (int i=0;i<64;i++){
      int idx=i*256+tid, tok=idx>>7, n=idx&127;
      int kh = n0+n;
      dst[((size_t)bm*Ln + l0+tok)*256 + kh] =
        __float2half_rn(Cs[tok*132+n] + bias[m*256+kh]);
    }
    __syncthreads();
  }
}

// ---------------- K2: bmm1 split-K, wmma. M=64 d, N=256 kh, K=256 l / split ----------------
__global__ void __launch_bounds__(256) k_gemm1w(){
  __shared__ __half As[32*72];
  __shared__ __half Bs2[32*264];
  const int bm = blockIdx.x, sp = blockIdx.y;
  const int b = bm>>3, m = bm&7;
  const int tid = threadIdx.x, wid = tid>>5;
  const int wm = wid&1, wn = wid>>1;
  wmma::fragment<wmma::accumulator,16,16,16,float> cf[2][4];
  #pragma unroll
  for (int r=0;r<2;r++)
    #pragma unroll
    for (int c=0;c<4;c++) wmma::fill_fragment(cf[r][c], 0.0f);
  for (int lc=0; lc<256; lc+=32){
    const int lb = sp*256 + lc;
    { int r=tid>>3, u=tid&7;
      *(uint4*)&As[r*72+u*8] =
        *(const uint4*)&g_xh[(size_t)(b*Ln+lb+r)*Dn + m*64 + u*8]; }
    #pragma unroll
    for (int i=0;i<4;i++){ int idx=i*256+tid, r=idx>>5, u=idx&31;
      *(uint4*)&Bs2[r*264+u*8] =
        *(const uint4*)&g_W1h[((size_t)bm*Ln+lb+r)*256 + u*8]; }
    __syncthreads();
    #pragma unroll
    for (int ks=0; ks<32; ks+=16){
      wmma::fragment<wmma::matrix_a,16,16,16,__half,wmma::col_major> af[2];
      wmma::fragment<wmma::matrix_b,16,16,16,__half,wmma::row_major> bf[4];
      #pragma unroll
      for (int r=0;r<2;r++)
        wmma::load_matrix_sync(af[r], &As[ks*72 + wm*32 + r*16], 72);
      #pragma unroll
      for (int c=0;c<4;c++)
        wmma::load_matrix_sync(bf[c], &Bs2[ks*264 + wn*64 + c*16], 264);
      #pragma unroll
      for (int r=0;r<2;r++)
        #pragma unroll
        for (int c=0;c<4;c++)
          wmma::mma_sync(cf[r][c], af[r], bf[c], cf[r][c]);
    }
    __syncthreads();
  }
  #pragma unroll
  for (int r=0;r<2;r++)
    #pragma unroll
    for (int c=0;c<4;c++)
      wmma::store_matrix_sync(
        &g_part[((size_t)(bm*8+sp)*64 + wm*32+r*16)*256 + wn*64 + c*16],
        cf[r][c], 256, wmma::mem_row_major);
}

// ---------------- K2b: reduce + gelu -> fp16 [bm][k][d] ----------------
__global__ void k_red1(){
  int g = blockIdx.x*256 + threadIdx.x;
  int bm = g>>14, r = g&16383;
  int k = r&255, d = r>>8;
  float s = 0.f;
  #pragma unroll
  for (int sp=0;sp<8;sp++)
    s += g_part[(size_t)((bm*8+sp)*64 + d)*KHn + k];
  g_out1h[(size_t)bm*16384 + k*64 + d] = __float2half_rn(gelu_f(s));
}

// ---------------- K3: bmm2, wmma. M=128 l, N=64 d, K=256 kh ----------------
__global__ void __launch_bounds__(256) k_gemm2w(){
  __shared__ char s2[34816];
  __half* A2 = (__half*)s2;          // 128 x 72
  __half* B2 = (__half*)(s2+18432);  // 64 x 72
  float*  C2 = (float*)s2;           // 128 x 68 (union)
  const int l0 = blockIdx.x*128, bm = blockIdx.y;
  const int b = bm>>3, m = bm&7;
  const int tid = threadIdx.x, wid = tid>>5;
  const int wm = wid&3, wn = wid>>2;
  wmma::fragment<wmma::accumulator,16,16,16,float> cf[2][2];
  #pragma unroll
  for (int r=0;r<2;r++)
    #pragma unroll
    for (int c=0;c<2;c++) wmma::fill_fragment(cf[r][c], 0.0f);
  for (int kc=0; kc<256; kc+=64){
    #pragma unroll
    for (int i=0;i<4;i++){ int idx=i*256+tid, row=idx>>3, u=idx&7;
      *(uint4*)&A2[row*72+u*8] =
        *(const uint4*)&g_W2h[((size_t)bm*Ln+l0+row)*256 + kc + u*8]; }
    #pragma unroll
    for (int i=0;i<2;i++){ int idx=i*256+tid, row=idx>>3, u=idx&7;
      *(uint4*)&B2[row*72+u*8] =
        *(const uint4*)&g_out1h[(size_t)bm*16384 + (kc+row)*64 + u*8]; }
    __syncthreads();
    #pragma unroll
    for (int ks=0; ks<64; ks+=16){
      wmma::fragment<wmma::matrix_a,16,16,16,__half,wmma::row_major> af[2];
      wmma::fragment<wmma::matrix_b,16,16,16,__half,wmma::row_major> bf[2];
      #pragma unroll
      for (int r=0;r<2;r++)
        wmma::load_matrix_sync(af[r], &A2[(wm*32+r*16)*72 + ks], 72);
      #pragma unroll
      for (int c=0;c<2;c++)
        wmma::load_matrix_sync(bf[c], &B2[ks*72 + wn*32 + c*16], 72);
      #pragma unroll
      for (int r=0;r<2;r++)
        #pragma unroll
        for (int c=0;c<2;c++)
          wmma::mma_sync(cf[r][c], af[r], bf[c], cf[r][c]);
    }
    __syncthreads();
  }
  #pragma unroll
  for (int r=0;r<2;r++)
    #pragma unroll
    for (int c=0;c<2;c++)
      wmma::store_matrix_sync(&C2[(wm*32+r*16)*68 + wn*32+c*16], cf[r][c], 68,
                              wmma::mem_row_major);
  __syncthreads();
  #pragma unroll
  for (int i=0;i<8;i++){
    int idx=i*256+tid, row=idx>>4, q=idx&15;
    *(float4*)&g_mixpre[(size_t)(b*Ln+l0+row)*Dn + m*64 + q*4] =
      *(const float4*)&C2[row*68 + q*4];
  }
}

// ---------------- block reduce (128 thr) ----------------
__device__ __forceinline__ float blkSum128(float v){
  __shared__ float red[4];
  #pragma unroll
  for (int o=16;o>0;o>>=1) v += __shfl_down_sync(0xffffffffu, v, o);
  if ((threadIdx.x & 31) == 0) red[threadIdx.x>>5] = v;
  __syncthreads();
  float s = red[0]+red[1]+red[2]+red[3];
  __syncthreads();
  return s;
}

// ---------------- K4: mix = LN(mixpre); ln1h = fp16(LN(mix)) ----------------
__global__ void __launch_bounds__(128) k_lnmix(
    const float* __restrict__ gm, const float* __restrict__ bb0,
    const float* __restrict__ g1, const float* __restrict__ b1){
  const int t = blockIdx.x, tid = threadIdx.x;
  float v[4];
  #pragma unroll
  for (int i=0;i<4;i++) v[i] = g_mixpre[(size_t)t*Dn + tid + i*128];
  float mean = blkSum128(v[0]+v[1]+v[2]+v[3]) * (1.f/512.f);
  float q = 0.f;
  #pragma unroll
  for (int i=0;i<4;i++){ float d=v[i]-mean; q += d*d; }
  float inv = rsqrtf(blkSum128(q)*(1.f/512.f) + 1e-5f);
  float mv[4];
  #pragma unroll
  for (int i=0;i<4;i++){
    int c = tid + i*128;
    mv[i] = (v[i]-mean)*inv*gm[c] + bb0[c];
    g_mix[(size_t)t*Dn + c] = mv[i];
  }
  float mean2 = blkSum128(mv[0]+mv[1]+mv[2]+mv[3]) * (1.f/512.f);
  float q2 = 0.f;
  #pragma unroll
  for (int i=0;i<4;i++){ float d=mv[i]-mean2; q2 += d*d; }
  float inv2 = rsqrtf(blkSum128(q2)*(1.f/512.f) + 1e-5f);
  #pragma unroll
  for (int i=0;i<4;i++){
    int c = tid + i*128;
    g_ln1h[(size_t)t*Dn + c] = __float2half_rn((mv[i]-mean2)*inv2*g1[c] + b1[c]);
  }
}

// ---------------- K5/K8: wmma fp16 GEMM (mode 0 = bneck+GLU, 1 = lin+residual) ----------------
#define HG_SMEM 67584

__global__ void __launch_bounds__(256) k_hgemm(int mode,
    const float* __restrict__ bias, float* __restrict__ extout){
  extern __shared__ char wsmraw[];
  __half* Ash = (__half*)wsmraw;                 // 128 x 40
  __half* Bsh = (__half*)(wsmraw + 128*40*2);    // 128 x 40
  float*  Cs  = (float*)wsmraw;                  // 128 x 132
  const int tid = threadIdx.x, wid = tid>>5;
  const int wm = wid & 3, wn = wid >> 2;
  const int t0 = blockIdx.x*128;
  const int e0 = blockIdx.y * (mode ? 128 : 64);
  const __half* Xh = mode ? g_acth : g_ln1h;
  const __half* Wh = mode ? g_lwh  : g_bwh;

  wmma::fragment<wmma::accumulator,16,16,16,float> cf[2][4];
  #pragma unroll
  for (int r=0;r<2;r++)
    #pragma unroll
    for (int c=0;c<4;c++) wmma::fill_fragment(cf[r][c], 0.0f);

  for (int kc = 0; kc < 512; kc += 32) {
    #pragma unroll
    for (int i=0;i<2;i++){ int idx=i*256+tid, r=idx>>2, u=idx&3;
      *(uint4*)&Ash[r*40 + u*8] = *(const uint4*)&Xh[(size_t)(t0+r)*512 + kc + u*8]; }
    #pragma unroll
    for (int i=0;i<2;i++){ int idx=i*256+tid, r=idx>>2, u=idx&3;
      int er = mode ? (e0 + r) : ((r < 64) ? (e0 + r) : (512 + e0 + (r - 64)));
      *(uint4*)&Bsh[r*40 + u*8] = *(const uint4*)&Wh[(size_t)er*512 + kc + u*8]; }
    __syncthreads();
    #pragma unroll
    for (int ks = 0; ks < 32; ks += 16) {
      wmma::fragment<wmma::matrix_a,16,16,16,__half,wmma::row_major> af[2];
      wmma::fragment<wmma::matrix_b,16,16,16,__half,wmma::col_major> bf[4];
      wmma::load_matrix_sync(af[0], &Ash[(wm*32    )*40 + ks], 40);
      wmma::load_matrix_sync(af[1], &Ash[(wm*32 + 16)*40 + ks], 40);
      #pragma unroll
      for (int c=0;c<4;c++)
        wmma::load_matrix_sync(bf[c], &Bsh[(wn*64 + c*16)*40 + ks], 40);
      #pragma unroll
      for (int r=0;r<2;r++)
        #pragma unroll
        for (int c=0;c<4;c++)
          wmma::mma_sync(cf[r][c], af[r], bf[c], cf[r][c]);
    }
    __syncthreads();
  }
  #pragma unroll
  for (int r=0;r<2;r++)
    #pragma unroll
    for (int c=0;c<4;c++)
      wmma::store_matrix_sync(&Cs[(wm*32 + r*16)*132 + wn*64 + c*16], cf[r][c],
                              132, wmma::mem_row_major);
  __syncthreads();

  if (mode == 0) {
    #pragma unroll
    for (int i=0;i<8;i++){
      int idx = i*256 + tid;
      int row = idx >> 4, jq = idx & 15;
      int j = jq*4;
      float4 ya = *(const float4*)&Cs[row*132 + j];
      float4 yb = *(const float4*)&Cs[row*132 + 64 + j];
      float4 ba = *(const float4*)&bias[e0 + j];
      float4 bbv= *(const float4*)&bias[512 + e0 + j];
      float4 o;
      o.x = (ya.x + ba.x) * (1.f/(1.f+expf(-(yb.x+bbv.x))));
      o.y = (ya.y + ba.y) * (1.f/(1.f+expf(-(yb.y+bbv.y))));
      o.z = (ya.z + ba.z) * (1.f/(1.f+expf(-(yb.z+bbv.z))));
      o.w = (ya.w + ba.w) * (1.f/(1.f+expf(-(yb.w+bbv.w))));
      *(float4*)&g_glu[(size_t)(t0+row)*512 + e0 + j] = o;
    }
  } else {
    #pragma unroll
    for (int i=0;i<16;i++){
      int idx = i*256 + tid;
      int row = idx >> 5, jq = idx & 31;
      int j = jq*4;
      size_t o = (size_t)(t0+row)*512 + e0 + j;
      float4 cv = *(const float4*)&Cs[row*132 + j];
      float4 mv = *(const float4*)&g_mix[o];
      float4 lb4= *(const float4*)&bias[e0 + j];
      float4 ov;
      ov.x = mv.x + cv.x + lb4.x;
      ov.y = mv.y + cv.y + lb4.y;
      ov.z = mv.z + cv.z + lb4.z;
      ov.w = mv.w + cv.w + lb4.w;
      *(float4*)&extout[o] = ov;
    }
  }
}

// ---------------- K6: depthwise conv ----------------
__global__ void __launch_bounds__(256) k_dwconv(
    const float* __restrict__ dww, const float* __restrict__ dwb){
  __shared__ float gs[94*64];
  const int b = blockIdx.z, c0 = blockIdx.y*64, l0 = blockIdx.x*64;
  const int tid = threadIdx.x, c = tid&63, lw = tid>>6;
  float w[31];
  #pragma unroll
  for (int j=0;j<31;j++) w[j] = dww[(c0+c)*31 + j];
  for (int i = tid; i < 94*64; i += 256){
    int row = i>>6, cc = i&63;
    int l = l0 - 15 + row;
    gs[i] = (l>=0 && l<Ln) ? g_glu[(size_t)(b*Ln + l)*Dn + c0+cc] : 0.f;
  }
  __syncthreads();
  float bv = dwb[c0+c];
  for (int lo=0; lo<16; lo++){
    int l = lo*4 + lw;
    float acc = bv;
    #pragma unroll
    for (int j=0;j<31;j++) acc += gs[(l+j)*64 + c] * w[j];
    g_dw[(size_t)(b*Ln + l0+l)*Dn + c0+c] = acc;
  }
}

// ---------------- K7: acth = fp16(gelu(LN(dw))) ----------------
__global__ void __launch_bounds__(128) k_ln2gelu(
    const float* __restrict__ g2, const float* __restrict__ b2){
  const int t = blockIdx.x, tid = threadIdx.x;
  float v[4];
  #pragma unroll
  for (int i=0;i<4;i++) v[i] = g_dw[(size_t)t*Dn + tid + i*128];
  float mean = blkSum128(v[0]+v[1]+v[2]+v[3]) * (1.f/512.f);
  float q = 0.f;
  #pragma unroll
  for (int i=0;i<4;i++){ float d=v[i]-mean; q += d*d; }
  float inv = rsqrtf(blkSum128(q)*(1.f/512.f) + 1e-5f);
  #pragma unroll
  for (int i=0;i<4;i++){
    int c = tid + i*128;
    g_acth[(size_t)t*Dn + c] = __float2half_rn(gelu_f((v[i]-mean)*inv*g2[c] + b2[c]));
  }
}

// ---------------- launch ----------------
extern "C" void kernel_launch(void* const* d_in, const int* in_sizes, int n_in,
                              void* d_out, int out_size) {
  const float* x      = (const float*)d_in[0];
  const float* w1f1w  = (const float*)d_in[1];
  const float* w1f1b  = (const float*)d_in[2];
  const float* w1f2w  = (const float*)d_in[3];
  const float* w1f2b  = (const float*)d_in[4];
  const float* w2f1w  = (const float*)d_in[5];
  const float* w2f1b  = (const float*)d_in[6];
  const float* w2f2w  = (const float*)d_in[7];
  const float* w2f2b  = (const float*)d_in[8];
  const float* lnmg   = (const float*)d_in[9];
  const float* lnmb   = (const float*)d_in[10];
  const float* ln1g   = (const float*)d_in[11];
  const float* ln1b   = (const float*)d_in[12];
  const float* bw     = (const float*)d_in[13];
  const float* bb     = (const float*)d_in[14];
  const float* dww    = (const float*)d_in[15];
  const float* dwb    = (const float*)d_in[16];
  const float* ln2g   = (const float*)d_in[17];
  const float* ln2b   = (const float*)d_in[18];
  const float* lw     = (const float*)d_in[19];
  const float* lb     = (const float*)d_in[20];
  float* out = (float*)d_out;

  cudaFuncSetAttribute(k_pmlpA, cudaFuncAttributeMaxDynamicSharedMemorySize, PA_SMEM);
  cudaFuncSetAttribute(k_pmlpB, cudaFuncAttributeMaxDynamicSharedMemorySize, PA_SMEM);
  cudaFuncSetAttribute(k_hgemm, cudaFuncAttributeMaxDynamicSharedMemorySize, HG_SMEM);

  __half* d_xh;     cudaGetSymbolAddress((void**)&d_xh,     g_xh);
  __half* d_w1f1h;  cudaGetSymbolAddress((void**)&d_w1f1h,  g_w1f1h);
  __half* d_w2f1h;  cudaGetSymbolAddress((void**)&d_w2f1h,  g_w2f1h);
  __half* d_w1f2h;  cudaGetSymbolAddress((void**)&d_w1f2h,  g_w1f2h);
  __half* d_w2f2h;  cudaGetSymbolAddress((void**)&d_w2f2h,  g_w2f2h);

  k_half<<<(Tn*Dn+255)/256, 256>>>(x, d_xh, Tn*Dn);
  k_half<<<128, 256>>>(w1f1w, d_w1f1h, Mn*64*64);
  k_half<<<128, 256>>>(w2f1w, d_w2f1h, Mn*64*64);
  k_half<<<512, 256>>>(w1f2w, d_w1f2h, Mn*256*64);
  k_half<<<512, 256>>>(w2f2w, d_w2f2h, Mn*256*64);
  k_convw<<<3072, 256>>>(bw, lw);

  k_pmlpA<<<dim3(16, 64), 256, PA_SMEM>>>(x, w1f1b, w2f1b);
  k_pmlpB<<<dim3(16, 128), 256, PA_SMEM>>>(w1f2b, w2f2b);
  k_gemm1w<<<dim3(BMn, 8), 256>>>();
  k_red1<<<4096, 256>>>();
  k_gemm2w<<<dim3(16, BMn), 256>>>();
  k_lnmix<<<Tn, 128>>>(lnmg, lnmb, ln1g, ln1b);
  k_hgemm<<<dim3(Tn/128, 8), 256, HG_SMEM>>>(0, bb, nullptr);
  k_dwconv<<<dim3(32, 8, 8), 256>>>(dww, dwb);
  k_ln2gelu<<<Tn, 128>>>(ln2g, ln2b);
  k_hgemm<<<dim3(Tn/128, 4), 256, HG_SMEM>>>(1, lb, out);
}

// round 10
// speedup vs baseline: 6.5085x; 1.0644x over previous
#include <cuda_runtime.h>
#include <cuda_fp16.h>
#include <mma.h>
#include <math.h>
#include <stdint.h>

using namespace nvcuda;

#define Bn 8
#define Ln 2048
#define Dn 512
#define Mn 8
#define KHn 256
#define BMn 64
#define Tn (Bn*Ln)

// ---------------- scratch ----------------
__device__ float  g_part[(size_t)BMn*8*64*KHn];  // [bm*8+sp][d][k] fp32 split-K partials
__device__ float  g_mixpre[(size_t)Tn*Dn];
__device__ float  g_mix [(size_t)Tn*Dn];
__device__ float  g_glu [(size_t)Tn*Dn];
__device__ float  g_dw  [(size_t)Tn*Dn];
__device__ float  g_pe  [(size_t)Ln*Dn];         // sinusoidal PE table
__device__ __half g_ln1h[(size_t)Tn*Dn];
__device__ __half g_acth[(size_t)Tn*Dn];
__device__ __half g_bwh [(size_t)1024*512];
__device__ __half g_lwh [(size_t)512*512];
__device__ __half g_xh  [(size_t)Tn*Dn];
__device__ __half g_w1f1h[(size_t)Mn*64*64];
__device__ __half g_w2f1h[(size_t)Mn*64*64];
__device__ __half g_w1f2h[(size_t)Mn*256*64];
__device__ __half g_w2f2h[(size_t)Mn*256*64];
__device__ __half g_hidh[(size_t)BMn*2*Ln*64];   // [(bm*2+net)][l][64]
__device__ __half g_W1h [(size_t)BMn*Ln*256];    // [bm][l][k]
__device__ __half g_W2h [(size_t)BMn*Ln*256];    // [bm][l][k]
__device__ __half g_out1h[(size_t)BMn*256*64];   // [bm][k][d]

__device__ __forceinline__ float gelu_f(float v){
  return 0.5f*v*(1.0f+erff(v*0.70710678118654752f));
}

// cp.async 16B helper
__device__ __forceinline__ void cpa16(void* dst, const void* src){
  uint32_t d;
  asm("{ .reg .u64 t; cvta.to.shared.u64 t, %1; cvt.u32.u64 %0, t; }" : "=r"(d) : "l"(dst));
  asm volatile("cp.async.ca.shared.global [%0], [%1], 16;" :: "r"(d), "l"(src));
}
#define CPA_COMMIT() asm volatile("cp.async.commit_group;")
#define CPA_WAIT1()  asm volatile("cp.async.wait_group 1;")
#define CPA_WAIT0()  asm volatile("cp.async.wait_group 0;")

// ---------------- fp32 -> fp16 converters ----------------
__global__ void k_half(const float* __restrict__ s, __half* __restrict__ d, int n){
  int i = blockIdx.x*256 + threadIdx.x;
  if (i < n) d[i] = __float2half_rn(s[i]);
}
__global__ void k_convw(const float* __restrict__ bw, const float* __restrict__ lw){
  int i = blockIdx.x*256 + threadIdx.x;
  if (i < 1024*512) g_bwh[i] = __float2half_rn(bw[i]);
  else              g_lwh[i - 1024*512] = __float2half_rn(lw[i - 1024*512]);
}

// ---------------- K0: sinusoidal PE table (fp32, [l][ch]) ----------------
__global__ void k_pe(){
  int i = blockIdx.x*256 + threadIdx.x;   // 1M entries
  int l = i >> 9, ch = i & 511;
  const float c0 = -9.210340371976184f / 512.0f;
  float ang = (float)l * expf((float)(ch & ~1) * c0);
  g_pe[i] = (ch & 1) ? cosf(ang) : sinf(ang);
}

// ---------------- K1a: hidden = gelu(fc1 @ (x+PE) + b), wmma ----------------
// grid (16 ltile, 64 bm), 256 thr. M=128 tok, N=128 (2 nets x 64 hid), K=64.
#define PA_SMEM (18432 + 67584)
__global__ void __launch_bounds__(256) k_pmlpA(
    const float* __restrict__ x,
    const float* __restrict__ b1f1, const float* __restrict__ b2f1){
  extern __shared__ char psm[];
  __half* Ah = (__half*)psm;             // 128 x 72
  __half* Bh = (__half*)(psm + 18432);   // 128 x 72 (n-major rows)
  float*  Cs = (float*)(psm + 18432);    // 128 x 132 (union with Bh)
  const int l0 = blockIdx.x*128;
  const int bm = blockIdx.y, b = bm>>3, m = bm&7;
  const int tid = threadIdx.x, wid = tid>>5;
  const int wm = wid&3, wn = wid>>2;

  #pragma unroll 4
  for (int i=0;i<32;i++){
    int idx=i*256+tid, tok=idx>>6, f=idx&63;
    int ch = m*64+f, l = l0+tok;
    Ah[tok*72+f] = __float2half_rn(x[(size_t)(b*Ln+l)*Dn+ch] + g_pe[(size_t)l*Dn+ch]);
  }
  #pragma unroll
  for (int i=0;i<4;i++){
    int idx=i*256+tid, n=idx>>3, u=idx&7;
    const __half* w = (n>=64)? g_w2f1h : g_w1f1h;
    *(uint4*)&Bh[n*72+u*8] = *(const uint4*)&w[m*4096 + (n&63)*64 + u*8];
  }
  __syncthreads();

  wmma::fragment<wmma::accumulator,16,16,16,float> cf[2][4];
  #pragma unroll
  for (int r=0;r<2;r++)
    #pragma unroll
    for (int c=0;c<4;c++) wmma::fill_fragment(cf[r][c], 0.0f);
  #pragma unroll
  for (int ks=0; ks<64; ks+=16){
    wmma::fragment<wmma::matrix_a,16,16,16,__half,wmma::row_major> af[2];
    wmma::fragment<wmma::matrix_b,16,16,16,__half,wmma::col_major> bf[4];
    #pragma unroll
    for (int r=0;r<2;r++)
      wmma::load_matrix_sync(af[r], &Ah[(wm*32+r*16)*72 + ks], 72);
    #pragma unroll
    for (int c=0;c<4;c++)
      wmma::load_matrix_sync(bf[c], &Bh[(wn*64+c*16)*72 + ks], 72);
    #pragma unroll
    for (int r=0;r<2;r++)
      #pragma unroll
      for (int c=0;c<4;c++)
        wmma::mma_sync(cf[r][c], af[r], bf[c], cf[r][c]);
  }
  __syncthreads();
  #pragma unroll
  for (int r=0;r<2;r++)
    #pragma unroll
    for (int c=0;c<4;c++)
      wmma::store_matrix_sync(&Cs[(wm*32+r*16)*132 + wn*64+c*16], cf[r][c], 132,
                              wmma::mem_row_major);
  __syncthreads();
  #pragma unroll 4
  for (int i=0;i<64;i++){
    int idx=i*256+tid, tok=idx>>7, n=idx&127;
    int net=n>>6, hid=n&63;
    float bias = net? b2f1[m*64+hid] : b1f1[m*64+hid];
    float v = gelu_f(Cs[tok*132+n] + bias);
    g_hidh[((size_t)(bm*2+net)*Ln + l0+tok)*64 + hid] = __float2half_rn(v);
  }
}

// ---------------- K1b: W = fc2 @ hidden + b, wmma ----------------
// grid (16 ltile, 128 bm*net), 256 thr. M=128 tok, N=256 (2 passes of 128), K=64.
__global__ void __launch_bounds__(256) k_pmlpB(
    const float* __restrict__ b1f2, const float* __restrict__ b2f2){
  extern __shared__ char psm[];
  __half* Ah = (__half*)psm;             // 128 x 72
  __half* Bh = (__half*)(psm + 18432);   // 128 x 72
  float*  Cs = (float*)(psm + 18432);    // 128 x 132
  const int l0 = blockIdx.x*128;
  const int bmnet = blockIdx.y, bm = bmnet>>1, net = bmnet&1, m = bm&7;
  const int tid = threadIdx.x, wid = tid>>5;
  const int wm = wid&3, wn = wid>>2;
  const __half* w = net? g_w2f2h : g_w1f2h;
  const float* bias = net? b2f2 : b1f2;
  __half* dst = net? g_W2h : g_W1h;

  #pragma unroll
  for (int i=0;i<4;i++){
    int idx=i*256+tid, row=idx>>3, u=idx&7;
    *(uint4*)&Ah[row*72+u*8] =
      *(const uint4*)&g_hidh[((size_t)(bm*2+net)*Ln + l0+row)*64 + u*8];
  }
  for (int pass=0; pass<2; pass++){
    const int n0 = pass*128;
    #pragma unroll
    for (int i=0;i<4;i++){
      int idx=i*256+tid, n=idx>>3, u=idx&7;
      *(uint4*)&Bh[n*72+u*8] = *(const uint4*)&w[m*16384 + (size_t)(n0+n)*64 + u*8];
    }
    __syncthreads();
    wmma::fragment<wmma::accumulator,16,16,16,float> cf[2][4];
    #pragma unroll
    for (int r=0;r<2;r++)
      #pragma unroll
      for (int c=0;c<4;c++) wmma::fill_fragment(cf[r][c], 0.0f);
    #pragma unroll
    for (int ks=0; ks<64; ks+=16){
      wmma::fragment<wmma::matrix_a,16,16,16,__half,wmma::row_major> af[2];
      wmma::fragment<wmma::matrix_b,16,16,16,__half,wmma::col_major> bf[4];
      #pragma unroll
      for (int r=0;r<2;r++)
        wmma::load_matrix_sync(af[r], &Ah[(wm*32+r*16)*72 + ks], 72);
      #pragma unroll
      for (int c=0;c<4;c++)
        wmma::load_matrix_sync(bf[c], &Bh[(wn*64+c*16)*72 + ks], 72);
      #pragma unroll
      for (int r=0;r<2;r++)
        #pragma unroll
        for (int c=0;c<4;c++)
          wmma::mma_sync(cf[r][c], af[r], bf[c], cf[r][c]);
    }
    __syncthreads();
    #pragma unroll
    for (int r=0;r<2;r++)
      #pragma unroll
      for (int c=0;c<4;c++)
        wmma::store_matrix_sync(&Cs[(wm*32+r*16)*132 + wn*64+c*16], cf[r][c], 132,
                                wmma::mem_row_major);
    __syncthreads();
    #pragma unroll 4
    for (int i=0;i<64;i++){
      int idx=i*256+tid, tok=idx>>7, n=idx&127;
      int kh = n0+n;
      dst[((size_t)bm*Ln + l0+tok)*256 + kh] =
        __float2half_rn(Cs[tok*132+n] + bias[m*256+kh]);
    }
    __syncthreads();
  }
}

// ---------------- K2: bmm1 split-K, wmma, 2-stage cp.async ----------------
__global__ void __launch_bounds__(256) k_gemm1w(){
  __shared__ __half As[2][32*72];
  __shared__ __half Bs2[2][32*264];
  const int bm = blockIdx.x, sp = blockIdx.y;
  const int b = bm>>3, m = bm&7;
  const int tid = threadIdx.x, wid = tid>>5;
  const int wm = wid&1, wn = wid>>1;

  auto load_stage = [&](int st, int lb){
    { int r=tid>>3, u=tid&7;
      cpa16(&As[st][r*72+u*8], &g_xh[(size_t)(b*Ln+lb+r)*Dn + m*64 + u*8]); }
    #pragma unroll
    for (int i=0;i<4;i++){ int idx=i*256+tid, r=idx>>5, u=idx&31;
      cpa16(&Bs2[st][r*264+u*8], &g_W1h[((size_t)bm*Ln+lb+r)*256 + u*8]); }
    CPA_COMMIT();
  };

  wmma::fragment<wmma::accumulator,16,16,16,float> cf[2][4];
  #pragma unroll
  for (int r=0;r<2;r++)
    #pragma unroll
    for (int c=0;c<4;c++) wmma::fill_fragment(cf[r][c], 0.0f);

  const int lbase = sp*256;
  load_stage(0, lbase);
  for (int ck=0; ck<8; ck++){
    if (ck+1 < 8) { load_stage((ck+1)&1, lbase + (ck+1)*32); CPA_WAIT1(); }
    else          { CPA_WAIT0(); }
    __syncthreads();
    const __half* Ac = As[ck&1];
    const __half* Bc = Bs2[ck&1];
    #pragma unroll
    for (int ks=0; ks<32; ks+=16){
      wmma::fragment<wmma::matrix_a,16,16,16,__half,wmma::col_major> af[2];
      wmma::fragment<wmma::matrix_b,16,16,16,__half,wmma::row_major> bf[4];
      #pragma unroll
      for (int r=0;r<2;r++)
        wmma::load_matrix_sync(af[r], &Ac[ks*72 + wm*32 + r*16], 72);
      #pragma unroll
      for (int c=0;c<4;c++)
        wmma::load_matrix_sync(bf[c], &Bc[ks*264 + wn*64 + c*16], 264);
      #pragma unroll
      for (int r=0;r<2;r++)
        #pragma unroll
        for (int c=0;c<4;c++)
          wmma::mma_sync(cf[r][c], af[r], bf[c], cf[r][c]);
    }
    __syncthreads();
  }
  #pragma unroll
  for (int r=0;r<2;r++)
    #pragma unroll
    for (int c=0;c<4;c++)
      wmma::store_matrix_sync(
        &g_part[((size_t)(bm*8+sp)*64 + wm*32+r*16)*256 + wn*64 + c*16],
        cf[r][c], 256, wmma::mem_row_major);
}

// ---------------- K2b: reduce + gelu -> fp16 [bm][k][d] ----------------
__global__ void k_red1(){
  int g = blockIdx.x*256 + threadIdx.x;
  int bm = g>>14, r = g&16383;
  int k = r&255, d = r>>8;
  float s = 0.f;
  #pragma unroll
  for (int sp=0;sp<8;sp++)
    s += g_part[(size_t)((bm*8+sp)*64 + d)*KHn + k];
  g_out1h[(size_t)bm*16384 + k*64 + d] = __float2half_rn(gelu_f(s));
}

// ---------------- K3: bmm2, wmma. M=128 l, N=64 d, K=256 kh ----------------
__global__ void __launch_bounds__(256) k_gemm2w(){
  __shared__ char s2[34816];
  __half* A2 = (__half*)s2;          // 128 x 72
  __half* B2 = (__half*)(s2+18432);  // 64 x 72
  float*  C2 = (float*)s2;           // 128 x 68 (union)
  const int l0 = blockIdx.x*128, bm = blockIdx.y;
  const int b = bm>>3, m = bm&7;
  const int tid = threadIdx.x, wid = tid>>5;
  const int wm = wid&3, wn = wid>>2;
  wmma::fragment<wmma::accumulator,16,16,16,float> cf[2][2];
  #pragma unroll
  for (int r=0;r<2;r++)
    #pragma unroll
    for (int c=0;c<2;c++) wmma::fill_fragment(cf[r][c], 0.0f);
  for (int kc=0; kc<256; kc+=64){
    #pragma unroll
    for (int i=0;i<4;i++){ int idx=i*256+tid, row=idx>>3, u=idx&7;
      *(uint4*)&A2[row*72+u*8] =
        *(const uint4*)&g_W2h[((size_t)bm*Ln+l0+row)*256 + kc + u*8]; }
    #pragma unroll
    for (int i=0;i<2;i++){ int idx=i*256+tid, row=idx>>3, u=idx&7;
      *(uint4*)&B2[row*72+u*8] =
        *(const uint4*)&g_out1h[(size_t)bm*16384 + (kc+row)*64 + u*8]; }
    __syncthreads();
    #pragma unroll
    for (int ks=0; ks<64; ks+=16){
      wmma::fragment<wmma::matrix_a,16,16,16,__half,wmma::row_major> af[2];
      wmma::fragment<wmma::matrix_b,16,16,16,__half,wmma::row_major> bf[2];
      #pragma unroll
      for (int r=0;r<2;r++)
        wmma::load_matrix_sync(af[r], &A2[(wm*32+r*16)*72 + ks], 72);
      #pragma unroll
      for (int c=0;c<2;c++)
        wmma::load_matrix_sync(bf[c], &B2[ks*72 + wn*32 + c*16], 72);
      #pragma unroll
      for (int r=0;r<2;r++)
        #pragma unroll
        for (int c=0;c<2;c++)
          wmma::mma_sync(cf[r][c], af[r], bf[c], cf[r][c]);
    }
    __syncthreads();
  }
  #pragma unroll
  for (int r=0;r<2;r++)
    #pragma unroll
    for (int c=0;c<2;c++)
      wmma::store_matrix_sync(&C2[(wm*32+r*16)*68 + wn*32+c*16], cf[r][c], 68,
                              wmma::mem_row_major);
  __syncthreads();
  #pragma unroll
  for (int i=0;i<8;i++){
    int idx=i*256+tid, row=idx>>4, q=idx&15;
    *(float4*)&g_mixpre[(size_t)(b*Ln+l0+row)*Dn + m*64 + q*4] =
      *(const float4*)&C2[row*68 + q*4];
  }
}

// ---------------- block reduce (128 thr) ----------------
__device__ __forceinline__ float blkSum128(float v){
  __shared__ float red[4];
  #pragma unroll
  for (int o=16;o>0;o>>=1) v += __shfl_down_sync(0xffffffffu, v, o);
  if ((threadIdx.x & 31) == 0) red[threadIdx.x>>5] = v;
  __syncthreads();
  float s = red[0]+red[1]+red[2]+red[3];
  __syncthreads();
  return s;
}

// ---------------- K4: mix = LN(mixpre); ln1h = fp16(LN(mix)) ----------------
__global__ void __launch_bounds__(128) k_lnmix(
    const float* __restrict__ gm, const float* __restrict__ bb0,
    const float* __restrict__ g1, const float* __restrict__ b1){
  const int t = blockIdx.x, tid = threadIdx.x;
  float v[4];
  #pragma unroll
  for (int i=0;i<4;i++) v[i] = g_mixpre[(size_t)t*Dn + tid + i*128];
  float mean = blkSum128(v[0]+v[1]+v[2]+v[3]) * (1.f/512.f);
  float q = 0.f;
  #pragma unroll
  for (int i=0;i<4;i++){ float d=v[i]-mean; q += d*d; }
  float inv = rsqrtf(blkSum128(q)*(1.f/512.f) + 1e-5f);
  float mv[4];
  #pragma unroll
  for (int i=0;i<4;i++){
    int c = tid + i*128;
    mv[i] = (v[i]-mean)*inv*gm[c] + bb0[c];
    g_mix[(size_t)t*Dn + c] = mv[i];
  }
  float mean2 = blkSum128(mv[0]+mv[1]+mv[2]+mv[3]) * (1.f/512.f);
  float q2 = 0.f;
  #pragma unroll
  for (int i=0;i<4;i++){ float d=mv[i]-mean2; q2 += d*d; }
  float inv2 = rsqrtf(blkSum128(q2)*(1.f/512.f) + 1e-5f);
  #pragma unroll
  for (int i=0;i<4;i++){
    int c = tid + i*128;
    g_ln1h[(size_t)t*Dn + c] = __float2half_rn((mv[i]-mean2)*inv2*g1[c] + b1[c]);
  }
}

// ---------------- K5/K8: wmma fp16 GEMM, 2-stage cp.async ----------------
// stage buffers: A 2x(128x40), B 2x(128x40) = 40960 B; C stage 128x132 f32 = 67584 B (union)
#define HG_SMEM 67584

__global__ void __launch_bounds__(256) k_hgemm(int mode,
    const float* __restrict__ bias, float* __restrict__ extout){
  extern __shared__ char wsmraw[];
  __half* Ast[2] = {(__half*)wsmraw,           (__half*)(wsmraw + 10240)};
  __half* Bst[2] = {(__half*)(wsmraw + 20480), (__half*)(wsmraw + 30720)};
  float*  Cs  = (float*)wsmraw;                 // 128 x 132
  const int tid = threadIdx.x, wid = tid>>5;
  const int wm = wid & 3, wn = wid >> 2;
  const int t0 = blockIdx.x*128;
  const int e0 = blockIdx.y * (mode ? 128 : 64);
  const __half* Xh = mode ? g_acth : g_ln1h;
  const __half* Wh = mode ? g_lwh  : g_bwh;

  auto load_stage = [&](int st, int kc){
    #pragma unroll
    for (int i=0;i<2;i++){ int idx=i*256+tid, r=idx>>2, u=idx&3;
      cpa16(&Ast[st][r*40 + u*8], &Xh[(size_t)(t0+r)*512 + kc + u*8]); }
    #pragma unroll
    for (int i=0;i<2;i++){ int idx=i*256+tid, r=idx>>2, u=idx&3;
      int er = mode ? (e0 + r) : ((r < 64) ? (e0 + r) : (512 + e0 + (r - 64)));
      cpa16(&Bst[st][r*40 + u*8], &Wh[(size_t)er*512 + kc + u*8]); }
    CPA_COMMIT();
  };

  wmma::fragment<wmma::accumulator,16,16,16,float> cf[2][4];
  #pragma unroll
  for (int r=0;r<2;r++)
    #pragma unroll
    for (int c=0;c<4;c++) wmma::fill_fragment(cf[r][c], 0.0f);

  load_stage(0, 0);
  for (int ck = 0; ck < 16; ck++) {
    if (ck+1 < 16) { load_stage((ck+1)&1, (ck+1)*32); CPA_WAIT1(); }
    else           { CPA_WAIT0(); }
    __syncthreads();
    const __half* Ac = Ast[ck&1];
    const __half* Bc = Bst[ck&1];
    #pragma unroll
    for (int ks = 0; ks < 32; ks += 16) {
      wmma::fragment<wmma::matrix_a,16,16,16,__half,wmma::row_major> af[2];
      wmma::fragment<wmma::matrix_b,16,16,16,__half,wmma::col_major> bf[4];
      wmma::load_matrix_sync(af[0], &Ac[(wm*32    )*40 + ks], 40);
      wmma::load_matrix_sync(af[1], &Ac[(wm*32 + 16)*40 + ks], 40);
      #pragma unroll
      for (int c=0;c<4;c++)
        wmma::load_matrix_sync(bf[c], &Bc[(wn*64 + c*16)*40 + ks], 40);
      #pragma unroll
      for (int r=0;r<2;r++)
        #pragma unroll
        for (int c=0;c<4;c++)
          wmma::mma_sync(cf[r][c], af[r], bf[c], cf[r][c]);
    }
    __syncthreads();
  }
  #pragma unroll
  for (int r=0;r<2;r++)
    #pragma unroll
    for (int c=0;c<4;c++)
      wmma::store_matrix_sync(&Cs[(wm*32 + r*16)*132 + wn*64 + c*16], cf[r][c],
                              132, wmma::mem_row_major);
  __syncthreads();

  if (mode == 0) {
    #pragma unroll
    for (int i=0;i<8;i++){
      int idx = i*256 + tid;
      int row = idx >> 4, jq = idx & 15;
      int j = jq*4;
      float4 ya = *(const float4*)&Cs[row*132 + j];
      float4 yb = *(const float4*)&Cs[row*132 + 64 + j];
      float4 ba = *(const float4*)&bias[e0 + j];
      float4 bbv= *(const float4*)&bias[512 + e0 + j];
      float4 o;
      o.x = (ya.x + ba.x) * (1.f/(1.f+expf(-(yb.x+bbv.x))));
      o.y = (ya.y + ba.y) * (1.f/(1.f+expf(-(yb.y+bbv.y))));
      o.z = (ya.z + ba.z) * (1.f/(1.f+expf(-(yb.z+bbv.z))));
      o.w = (ya.w + ba.w) * (1.f/(1.f+expf(-(yb.w+bbv.w))));
      *(float4*)&g_glu[(size_t)(t0+row)*512 + e0 + j] = o;
    }
  } else {
    #pragma unroll
    for (int i=0;i<16;i++){
      int idx = i*256 + tid;
      int row = idx >> 5, jq = idx & 31;
      int j = jq*4;
      size_t o = (size_t)(t0+row)*512 + e0 + j;
      float4 cv = *(const float4*)&Cs[row*132 + j];
      float4 mv = *(const float4*)&g_mix[o];
      float4 lb4= *(const float4*)&bias[e0 + j];
      float4 ov;
      ov.x = mv.x + cv.x + lb4.x;
      ov.y = mv.y + cv.y + lb4.y;
      ov.z = mv.z + cv.z + lb4.z;
      ov.w = mv.w + cv.w + lb4.w;
      *(float4*)&extout[o] = ov;
    }
  }
}

// ---------------- K6: depthwise conv ----------------
__global__ void __launch_bounds__(256) k_dwconv(
    const float* __restrict__ dww, const float* __restrict__ dwb){
  __shared__ float gs[94*64];
  const int b = blockIdx.z, c0 = blockIdx.y*64, l0 = blockIdx.x*64;
  const int tid = threadIdx.x, c = tid&63, lw = tid>>6;
  float w[31];
  #pragma unroll
  for (int j=0;j<31;j++) w[j] = dww[(c0+c)*31 + j];
  for (int i = tid; i < 94*64; i += 256){
    int row = i>>6, cc = i&63;
    int l = l0 - 15 + row;
    gs[i] = (l>=0 && l<Ln) ? g_glu[(size_t)(b*Ln + l)*Dn + c0+cc] : 0.f;
  }
  __syncthreads();
  float bv = dwb[c0+c];
  for (int lo=0; lo<16; lo++){
    int l = lo*4 + lw;
    float acc = bv;
    #pragma unroll
    for (int j=0;j<31;j++) acc += gs[(l+j)*64 + c] * w[j];
    g_dw[(size_t)(b*Ln + l0+l)*Dn + c0+c] = acc;
  }
}

// ---------------- K7: acth = fp16(gelu(LN(dw))) ----------------
__global__ void __launch_bounds__(128) k_ln2gelu(
    const float* __restrict__ g2, const float* __restrict__ b2){
  const int t = blockIdx.x, tid = threadIdx.x;
  float v[4];
  #pragma unroll
  for (int i=0;i<4;i++) v[i] = g_dw[(size_t)t*Dn + tid + i*128];
  float mean = blkSum128(v[0]+v[1]+v[2]+v[3]) * (1.f/512.f);
  float q = 0.f;
  #pragma unroll
  for (int i=0;i<4;i++){ float d=v[i]-mean; q += d*d; }
  float inv = rsqrtf(blkSum128(q)*(1.f/512.f) + 1e-5f);
  #pragma unroll
  for (int i=0;i<4;i++){
    int c = tid + i*128;
    g_acth[(size_t)t*Dn + c] = __float2half_rn(gelu_f((v[i]-mean)*inv*g2[c] + b2[c]));
  }
}

// ---------------- launch ----------------
extern "C" void kernel_launch(void* const* d_in, const int* in_sizes, int n_in,
                              void* d_out, int out_size) {
  const float* x      = (const float*)d_in[0];
  const float* w1f1w  = (const float*)d_in[1];
  const float* w1f1b  = (const float*)d_in[2];
  const float* w1f2w  = (const float*)d_in[3];
  const float* w1f2b  = (const float*)d_in[4];
  const float* w2f1w  = (const float*)d_in[5];
  const float* w2f1b  = (const float*)d_in[6];
  const float* w2f2w  = (const float*)d_in[7];
  const float* w2f2b  = (const float*)d_in[8];
  const float* lnmg   = (const float*)d_in[9];
  const float* lnmb   = (const float*)d_in[10];
  const float* ln1g   = (const float*)d_in[11];
  const float* ln1b   = (const float*)d_in[12];
  const float* bw     = (const float*)d_in[13];
  const float* bb     = (const float*)d_in[14];
  const float* dww    = (const float*)d_in[15];
  const float* dwb    = (const float*)d_in[16];
  const float* ln2g   = (const float*)d_in[17];
  const float* ln2b   = (const float*)d_in[18];
  const float* lw     = (const float*)d_in[19];
  const float* lb     = (const float*)d_in[20];
  float* out = (float*)d_out;

  cudaFuncSetAttribute(k_pmlpA, cudaFuncAttributeMaxDynamicSharedMemorySize, PA_SMEM);
  cudaFuncSetAttribute(k_pmlpB, cudaFuncAttributeMaxDynamicSharedMemorySize, PA_SMEM);
  cudaFuncSetAttribute(k_hgemm, cudaFuncAttributeMaxDynamicSharedMemorySize, HG_SMEM);

  __half* d_xh;     cudaGetSymbolAddress((void**)&d_xh,     g_xh);
  __half* d_w1f1h;  cudaGetSymbolAddress((void**)&d_w1f1h,  g_w1f1h);
  __half* d_w2f1h;  cudaGetSymbolAddress((void**)&d_w2f1h,  g_w2f1h);
  __half* d_w1f2h;  cudaGetSymbolAddress((void**)&d_w1f2h,  g_w1f2h);
  __half* d_w2f2h;  cudaGetSymbolAddress((void**)&d_w2f2h,  g_w2f2h);

  k_pe<<<4096, 256>>>();
  k_half<<<(Tn*Dn+255)/256, 256>>>(x, d_xh, Tn*Dn);
  k_half<<<128, 256>>>(w1f1w, d_w1f1h, Mn*64*64);
  k_half<<<128, 256>>>(w2f1w, d_w2f1h, Mn*64*64);
  k_half<<<512, 256>>>(w1f2w, d_w1f2h, Mn*256*64);
  k_half<<<512, 256>>>(w2f2w, d_w2f2h, Mn*256*64);
  k_convw<<<3072, 256>>>(bw, lw);

  k_pmlpA<<<dim3(16, 64), 256, PA_SMEM>>>(x, w1f1b, w2f1b);
  k_pmlpB<<<dim3(16, 128), 256, PA_SMEM>>>(w1f2b, w2f2b);
  k_gemm1w<<<dim3(BMn, 8), 256>>>();
  k_red1<<<4096, 256>>>();
  k_gemm2w<<<dim3(16, BMn), 256>>>();
  k_lnmix<<<Tn, 128>>>(lnmg, lnmb, ln1g, ln1b);
  k_hgemm<<<dim3(Tn/128, 8), 256, HG_SMEM>>>(0, bb, nullptr);
  k_dwconv<<<dim3(32, 8, 8), 256>>>(dww, dwb);
  k_ln2gelu<<<Tn, 128>>>(ln2g, ln2b);
  k_hgemm<<<dim3(Tn/128, 4), 256, HG_SMEM>>>(1, lb, out);
}

// round 12
// speedup vs baseline: 6.8039x; 1.0454x over previous
#include <cuda_runtime.h>
#include <cuda_fp16.h>
#include <mma.h>
#include <math.h>
#include <stdint.h>

using namespace nvcuda;

#define Bn 8
#define Ln 2048
#define Dn 512
#define Mn 8
#define KHn 256
#define BMn 64
#define Tn (Bn*Ln)

// ---------------- scratch ----------------
__device__ float  g_part[(size_t)BMn*8*64*KHn];  // [bm*8+sp][d][k] fp32 split-K partials
__device__ float  g_mixpre[(size_t)Tn*Dn];
__device__ float  g_mix [(size_t)Tn*Dn];
__device__ float  g_pe  [(size_t)Ln*Dn];         // sinusoidal PE table
__device__ __half g_gluh[(size_t)Tn*Dn];
__device__ __half g_ln1h[(size_t)Tn*Dn];
__device__ __half g_acth[(size_t)Tn*Dn];
__device__ __half g_bwh [(size_t)1024*512];
__device__ __half g_lwh [(size_t)512*512];
__device__ __half g_xh  [(size_t)Tn*Dn];
__device__ __half g_w1f1h[(size_t)Mn*64*64];
__device__ __half g_w2f1h[(size_t)Mn*64*64];
__device__ __half g_w1f2h[(size_t)Mn*256*64];
__device__ __half g_w2f2h[(size_t)Mn*256*64];
__device__ __half g_hidh[(size_t)BMn*2*Ln*64];   // [(bm*2+net)][l][64]
__device__ __half g_W1h [(size_t)BMn*Ln*256];    // [bm][l][k]
__device__ __half g_W2h [(size_t)BMn*Ln*256];    // [bm][l][k]
__device__ __half g_out1h[(size_t)BMn*256*64];   // [bm][k][d]

__device__ __forceinline__ float gelu_f(float v){
  return 0.5f*v*(1.0f+erff(v*0.70710678118654752f));
}

// cp.async 16B helper
__device__ __forceinline__ void cpa16(void* dst, const void* src){
  uint32_t d;
  asm("{ .reg .u64 t; cvta.to.shared.u64 t, %1; cvt.u32.u64 %0, t; }" : "=r"(d) : "l"(dst));
  asm volatile("cp.async.ca.shared.global [%0], [%1], 16;" :: "r"(d), "l"(src));
}
#define CPA_COMMIT() asm volatile("cp.async.commit_group;")
#define CPA_WAIT1()  asm volatile("cp.async.wait_group 1;")
#define CPA_WAIT0()  asm volatile("cp.async.wait_group 0;")

// ---------------- K0: fused prep (PE table + all fp16 conversions) ----------------
// segments: pe 1048576 | xh 8388608 | w1f1 32768 | w2f1 32768 | w1f2 131072
//           | w2f2 131072 | bw 524288 | lw 262144   -> total 10551296 = 41216*256
__global__ void k_prep(const float* __restrict__ x,
    const float* __restrict__ w1f1w, const float* __restrict__ w2f1w,
    const float* __restrict__ w1f2w, const float* __restrict__ w2f2w,
    const float* __restrict__ bw, const float* __restrict__ lw){
  int i = blockIdx.x*256 + threadIdx.x;
  if (i < 1048576){
    int l = i>>9, ch = i&511;
    const float c0 = -9.210340371976184f / 512.0f;
    float ang = (float)l * expf((float)(ch & ~1) * c0);
    g_pe[i] = (ch & 1) ? cosf(ang) : sinf(ang);
    return;
  }
  i -= 1048576;
  if (i < 8388608){ g_xh[i] = __float2half_rn(x[i]); return; }
  i -= 8388608;
  if (i < 32768){ g_w1f1h[i] = __float2half_rn(w1f1w[i]); return; }
  i -= 32768;
  if (i < 32768){ g_w2f1h[i] = __float2half_rn(w2f1w[i]); return; }
  i -= 32768;
  if (i < 131072){ g_w1f2h[i] = __float2half_rn(w1f2w[i]); return; }
  i -= 131072;
  if (i < 131072){ g_w2f2h[i] = __float2half_rn(w2f2w[i]); return; }
  i -= 131072;
  if (i < 524288){ g_bwh[i] = __float2half_rn(bw[i]); return; }
  i -= 524288;
  g_lwh[i] = __float2half_rn(lw[i]);
}

// ---------------- K1a: hidden = gelu(fc1 @ (x+PE) + b), wmma ----------------
#define PA_SMEM (18432 + 67584)
__global__ void __launch_bounds__(256) k_pmlpA(
    const float* __restrict__ x,
    const float* __restrict__ b1f1, const float* __restrict__ b2f1){
  extern __shared__ char psm[];
  __half* Ah = (__half*)psm;             // 128 x 72
  __half* Bh = (__half*)(psm + 18432);   // 128 x 72
  float*  Cs = (float*)(psm + 18432);    // 128 x 132 (union with Bh)
  const int l0 = blockIdx.x*128;
  const int bm = blockIdx.y, b = bm>>3, m = bm&7;
  const int tid = threadIdx.x, wid = tid>>5;
  const int wm = wid&3, wn = wid>>2;

  #pragma unroll 4
  for (int i=0;i<32;i++){
    int idx=i*256+tid, tok=idx>>6, f=idx&63;
    int ch = m*64+f, l = l0+tok;
    Ah[tok*72+f] = __float2half_rn(x[(size_t)(b*Ln+l)*Dn+ch] + g_pe[(size_t)l*Dn+ch]);
  }
  #pragma unroll
  for (int i=0;i<4;i++){
    int idx=i*256+tid, n=idx>>3, u=idx&7;
    const __half* w = (n>=64)? g_w2f1h : g_w1f1h;
    *(uint4*)&Bh[n*72+u*8] = *(const uint4*)&w[m*4096 + (n&63)*64 + u*8];
  }
  __syncthreads();

  wmma::fragment<wmma::accumulator,16,16,16,float> cf[2][4];
  #pragma unroll
  for (int r=0;r<2;r++)
    #pragma unroll
    for (int c=0;c<4;c++) wmma::fill_fragment(cf[r][c], 0.0f);
  #pragma unroll
  for (int ks=0; ks<64; ks+=16){
    wmma::fragment<wmma::matrix_a,16,16,16,__half,wmma::row_major> af[2];
    wmma::fragment<wmma::matrix_b,16,16,16,__half,wmma::col_major> bf[4];
    #pragma unroll
    for (int r=0;r<2;r++)
      wmma::load_matrix_sync(af[r], &Ah[(wm*32+r*16)*72 + ks], 72);
    #pragma unroll
    for (int c=0;c<4;c++)
      wmma::load_matrix_sync(bf[c], &Bh[(wn*64+c*16)*72 + ks], 72);
    #pragma unroll
    for (int r=0;r<2;r++)
      #pragma unroll
      for (int c=0;c<4;c++)
        wmma::mma_sync(cf[r][c], af[r], bf[c], cf[r][c]);
  }
  __syncthreads();
  #pragma unroll
  for (int r=0;r<2;r++)
    #pragma unroll
    for (int c=0;c<4;c++)
      wmma::store_matrix_sync(&Cs[(wm*32+r*16)*132 + wn*64+c*16], cf[r][c], 132,
                              wmma::mem_row_major);
  __syncthreads();
  #pragma unroll 4
  for (int i=0;i<64;i++){
    int idx=i*256+tid, tok=idx>>7, n=idx&127;
    int net=n>>6, hid=n&63;
    float bias = net? b2f1[m*64+hid] : b1f1[m*64+hid];
    float v = gelu_f(Cs[tok*132+n] + bias);
    g_hidh[((size_t)(bm*2+net)*Ln + l0+tok)*64 + hid] = __float2half_rn(v);
  }
}

// ---------------- K1b: W = fc2 @ hidden + b, wmma ----------------
__global__ void __launch_bounds__(256) k_pmlpB(
    const float* __restrict__ b1f2, const float* __restrict__ b2f2){
  extern __shared__ char psm[];
  __half* Ah = (__half*)psm;             // 128 x 72
  __half* Bh = (__half*)(psm + 18432);   // 128 x 72
  float*  Cs = (float*)(psm + 18432);    // 128 x 132
  const int l0 = blockIdx.x*128;
  const int bmnet = blockIdx.y, bm = bmnet>>1, net = bmnet&1, m = bm&7;
  const int tid = threadIdx.x, wid = tid>>5;
  const int wm = wid&3, wn = wid>>2;
  const __half* w = net? g_w2f2h : g_w1f2h;
  const float* bias = net? b2f2 : b1f2;
  __half* dst = net? g_W2h : g_W1h;

  #pragma unroll
  for (int i=0;i<4;i++){
    int idx=i*256+tid, row=idx>>3, u=idx&7;
    *(uint4*)&Ah[row*72+u*8] =
      *(const uint4*)&g_hidh[((size_t)(bm*2+net)*Ln + l0+row)*64 + u*8];
  }
  for (int pass=0; pass<2; pass++){
    const int n0 = pass*128;
    #pragma unroll
    for (int i=0;i<4;i++){
      int idx=i*256+tid, n=idx>>3, u=idx&7;
      *(uint4*)&Bh[n*72+u*8] = *(const uint4*)&w[m*16384 + (size_t)(n0+n)*64 + u*8];
    }
    __syncthreads();
    wmma::fragment<wmma::accumulator,16,16,16,float> cf[2][4];
    #pragma unroll
    for (int r=0;r<2;r++)
      #pragma unroll
      for (int c=0;c<4;c++) wmma::fill_fragment(cf[r][c], 0.0f);
    #pragma unroll
    for (int ks=0; ks<64; ks+=16){
      wmma::fragment<wmma::matrix_a,16,16,16,__half,wmma::row_major> af[2];
      wmma::fragment<wmma::matrix_b,16,16,16,__half,wmma::col_major> bf[4];
      #pragma unroll
      for (int r=0;r<2;r++)
        wmma::load_matrix_sync(af[r], &Ah[(wm*32+r*16)*72 + ks], 72);
      #pragma unroll
      for (int c=0;c<4;c++)
        wmma::load_matrix_sync(bf[c], &Bh[(wn*64+c*16)*72 + ks], 72);
      #pragma unroll
      for (int r=0;r<2;r++)
        #pragma unroll
        for (int c=0;c<4;c++)
          wmma::mma_sync(cf[r][c], af[r], bf[c], cf[r][c]);
    }
    __syncthreads();
    #pragma unroll
    for (int r=0;r<2;r++)
      #pragma unroll
      for (int c=0;c<4;c++)
        wmma::store_matrix_sync(&Cs[(wm*32+r*16)*132 + wn*64+c*16], cf[r][c], 132,
                                wmma::mem_row_major);
    __syncthreads();
    #pragma unroll 4
    for (int i=0;i<64;i++){
      int idx=i*256+tid, tok=idx>>7, n=idx&127;
      int kh = n0+n;
      dst[((size_t)bm*Ln + l0+tok)*256 + kh] =
        __float2half_rn(Cs[tok*132+n] + bias[m*256+kh]);
    }
    __syncthreads();
  }
}

// ---------------- K2: bmm1 split-K, wmma, 2-stage cp.async ----------------
__global__ void __launch_bounds__(256) k_gemm1w(){
  __shared__ __half As[2][32*72];
  __shared__ __half Bs2[2][32*264];
  const int bm = blockIdx.x, sp = blockIdx.y;
  const int b = bm>>3, m = bm&7;
  const int tid = threadIdx.x, wid = tid>>5;
  const int wm = wid&1, wn = wid>>1;

  auto load_stage = [&](int st, int lb){
    { int r=tid>>3, u=tid&7;
      cpa16(&As[st][r*72+u*8], &g_xh[(size_t)(b*Ln+lb+r)*Dn + m*64 + u*8]); }
    #pragma unroll
    for (int i=0;i<4;i++){ int idx=i*256+tid, r=idx>>5, u=idx&31;
      cpa16(&Bs2[st][r*264+u*8], &g_W1h[((size_t)bm*Ln+lb+r)*256 + u*8]); }
    CPA_COMMIT();
  };

  wmma::fragment<wmma::accumulator,16,16,16,float> cf[2][4];
  #pragma unroll
  for (int r=0;r<2;r++)
    #pragma unroll
    for (int c=0;c<4;c++) wmma::fill_fragment(cf[r][c], 0.0f);

  const int lbase = sp*256;
  load_stage(0, lbase);
  for (int ck=0; ck<8; ck++){
    if (ck+1 < 8) { load_stage((ck+1)&1, lbase + (ck+1)*32); CPA_WAIT1(); }
    else          { CPA_WAIT0(); }
    __syncthreads();
    const __half* Ac = As[ck&1];
    const __half* Bc = Bs2[ck&1];
    #pragma unroll
    for (int ks=0; ks<32; ks+=16){
      wmma::fragment<wmma::matrix_a,16,16,16,__half,wmma::col_major> af[2];
      wmma::fragment<wmma::matrix_b,16,16,16,__half,wmma::row_major> bf[4];
      #pragma unroll
      for (int r=0;r<2;r++)
        wmma::load_matrix_sync(af[r], &Ac[ks*72 + wm*32 + r*16], 72);
      #pragma unroll
      for (int c=0;c<4;c++)
        wmma::load_matrix_sync(bf[c], &Bc[ks*264 + wn*64 + c*16], 264);
      #pragma unroll
      for (int r=0;r<2;r++)
        #pragma unroll
        for (int c=0;c<4;c++)
          wmma::mma_sync(cf[r][c], af[r], bf[c], cf[r][c]);
    }
    __syncthreads();
  }
  #pragma unroll
  for (int r=0;r<2;r++)
    #pragma unroll
    for (int c=0;c<4;c++)
      wmma::store_matrix_sync(
        &g_part[((size_t)(bm*8+sp)*64 + wm*32+r*16)*256 + wn*64 + c*16],
        cf[r][c], 256, wmma::mem_row_major);
}

// ---------------- K2b: reduce + gelu -> fp16 [bm][k][d] ----------------
__global__ void k_red1(){
  int g = blockIdx.x*256 + threadIdx.x;
  int bm = g>>14, r = g&16383;
  int k = r&255, d = r>>8;
  float s = 0.f;
  #pragma unroll
  for (int sp=0;sp<8;sp++)
    s += g_part[(size_t)((bm*8+sp)*64 + d)*KHn + k];
  g_out1h[(size_t)bm*16384 + k*64 + d] = __float2half_rn(gelu_f(s));
}

// ---------------- K3: bmm2, wmma. M=128 l, N=64 d, K=256 kh ----------------
__global__ void __launch_bounds__(256) k_gemm2w(){
  __shared__ char s2[34816];
  __half* A2 = (__half*)s2;          // 128 x 72
  __half* B2 = (__half*)(s2+18432);  // 64 x 72
  float*  C2 = (float*)s2;           // 128 x 68 (union)
  const int l0 = blockIdx.x*128, bm = blockIdx.y;
  const int b = bm>>3, m = bm&7;
  const int tid = threadIdx.x, wid = tid>>5;
  const int wm = wid&3, wn = wid>>2;
  wmma::fragment<wmma::accumulator,16,16,16,float> cf[2][2];
  #pragma unroll
  for (int r=0;r<2;r++)
    #pragma unroll
    for (int c=0;c<2;c++) wmma::fill_fragment(cf[r][c], 0.0f);
  for (int kc=0; kc<256; kc+=64){
    #pragma unroll
    for (int i=0;i<4;i++){ int idx=i*256+tid, row=idx>>3, u=idx&7;
      *(uint4*)&A2[row*72+u*8] =
        *(const uint4*)&g_W2h[((size_t)bm*Ln+l0+row)*256 + kc + u*8]; }
    #pragma unroll
    for (int i=0;i<2;i++){ int idx=i*256+tid, row=idx>>3, u=idx&7;
      *(uint4*)&B2[row*72+u*8] =
        *(const uint4*)&g_out1h[(size_t)bm*16384 + (kc+row)*64 + u*8]; }
    __syncthreads();
    #pragma unroll
    for (int ks=0; ks<64; ks+=16){
      wmma::fragment<wmma::matrix_a,16,16,16,__half,wmma::row_major> af[2];
      wmma::fragment<wmma::matrix_b,16,16,16,__half,wmma::row_major> bf[2];
      #pragma unroll
      for (int r=0;r<2;r++)
        wmma::load_matrix_sync(af[r], &A2[(wm*32+r*16)*72 + ks], 72);
      #pragma unroll
      for (int c=0;c<2;c++)
        wmma::load_matrix_sync(bf[c], &B2[ks*72 + wn*32 + c*16], 72);
      #pragma unroll
      for (int r=0;r<2;r++)
        #pragma unroll
        for (int c=0;c<2;c++)
          wmma::mma_sync(cf[r][c], af[r], bf[c], cf[r][c]);
    }
    __syncthreads();
  }
  #pragma unroll
  for (int r=0;r<2;r++)
    #pragma unroll
    for (int c=0;c<2;c++)
      wmma::store_matrix_sync(&C2[(wm*32+r*16)*68 + wn*32+c*16], cf[r][c], 68,
                              wmma::mem_row_major);
  __syncthreads();
  #pragma unroll
  for (int i=0;i<8;i++){
    int idx=i*256+tid, row=idx>>4, q=idx&15;
    *(float4*)&g_mixpre[(size_t)(b*Ln+l0+row)*Dn + m*64 + q*4] =
      *(const float4*)&C2[row*68 + q*4];
  }
}

// ---------------- block reduce (128 thr) ----------------
__device__ __forceinline__ float blkSum128(float v){
  __shared__ float red[4];
  #pragma unroll
  for (int o=16;o>0;o>>=1) v += __shfl_down_sync(0xffffffffu, v, o);
  if ((threadIdx.x & 31) == 0) red[threadIdx.x>>5] = v;
  __syncthreads();
  float s = red[0]+red[1]+red[2]+red[3];
  __syncthreads();
  return s;
}

// ---------------- K4: mix = LN(mixpre); ln1h = fp16(LN(mix)) ----------------
__global__ void __launch_bounds__(128) k_lnmix(
    const float* __restrict__ gm, const float* __restrict__ bb0,
    const float* __restrict__ g1, const float* __restrict__ b1){
  const int t = blockIdx.x, tid = threadIdx.x;
  float v[4];
  #pragma unroll
  for (int i=0;i<4;i++) v[i] = g_mixpre[(size_t)t*Dn + tid + i*128];
  float mean = blkSum128(v[0]+v[1]+v[2]+v[3]) * (1.f/512.f);
  float q = 0.f;
  #pragma unroll
  for (int i=0;i<4;i++){ float d=v[i]-mean; q += d*d; }
  float inv = rsqrtf(blkSum128(q)*(1.f/512.f) + 1e-5f);
  float mv[4];
  #pragma unroll
  for (int i=0;i<4;i++){
    int c = tid + i*128;
    mv[i] = (v[i]-mean)*inv*gm[c] + bb0[c];
    g_mix[(size_t)t*Dn + c] = mv[i];
  }
  float mean2 = blkSum128(mv[0]+mv[1]+mv[2]+mv[3]) * (1.f/512.f);
  float q2 = 0.f;
  #pragma unroll
  for (int i=0;i<4;i++){ float d=mv[i]-mean2; q2 += d*d; }
  float inv2 = rsqrtf(blkSum128(q2)*(1.f/512.f) + 1e-5f);
  #pragma unroll
  for (int i=0;i<4;i++){
    int c = tid + i*128;
    g_ln1h[(size_t)t*Dn + c] = __float2half_rn((mv[i]-mean2)*inv2*g1[c] + b1[c]);
  }
}

// ---------------- K5/K8: wmma fp16 GEMM, 2-stage cp.async, K-chunk 64 ----------------
// stages: A 2x(128x72)=36864, B 2x(128x72)=36864 -> 73728 B; Cs 128x132 f32 = 67584 (union)
#define HG_SMEM 73728

__global__ void __launch_bounds__(256) k_hgemm(int mode,
    const float* __restrict__ bias, float* __restrict__ extout){
  extern __shared__ char wsmraw[];
  __half* Ast[2] = {(__half*)wsmraw,           (__half*)(wsmraw + 18432)};
  __half* Bst[2] = {(__half*)(wsmraw + 36864), (__half*)(wsmraw + 55296)};
  float*  Cs  = (float*)wsmraw;                 // 128 x 132
  const int tid = threadIdx.x, wid = tid>>5;
  const int wm = wid & 3, wn = wid >> 2;
  const int t0 = blockIdx.x*128;
  const int e0 = blockIdx.y * (mode ? 128 : 64);
  const __half* Xh = mode ? g_acth : g_ln1h;
  const __half* Wh = mode ? g_lwh  : g_bwh;

  auto load_stage = [&](int st, int kc){
    #pragma unroll
    for (int i=0;i<4;i++){ int idx=i*256+tid, r=idx>>3, u=idx&7;
      cpa16(&Ast[st][r*72 + u*8], &Xh[(size_t)(t0+r)*512 + kc + u*8]); }
    #pragma unroll
    for (int i=0;i<4;i++){ int idx=i*256+tid, r=idx>>3, u=idx&7;
      int er = mode ? (e0 + r) : ((r < 64) ? (e0 + r) : (512 + e0 + (r - 64)));
      cpa16(&Bst[st][r*72 + u*8], &Wh[(size_t)er*512 + kc + u*8]); }
    CPA_COMMIT();
  };

  wmma::fragment<wmma::accumulator,16,16,16,float> cf[2][4];
  #pragma unroll
  for (int r=0;r<2;r++)
    #pragma unroll
    for (int c=0;c<4;c++) wmma::fill_fragment(cf[r][c], 0.0f);

  load_stage(0, 0);
  for (int ck = 0; ck < 8; ck++) {
    if (ck+1 < 8) { load_stage((ck+1)&1, (ck+1)*64); CPA_WAIT1(); }
    else          { CPA_WAIT0(); }
    __syncthreads();
    const __half* Ac = Ast[ck&1];
    const __half* Bc = Bst[ck&1];
    #pragma unroll
    for (int ks = 0; ks < 64; ks += 16) {
      wmma::fragment<wmma::matrix_a,16,16,16,__half,wmma::row_major> af[2];
      wmma::fragment<wmma::matrix_b,16,16,16,__half,wmma::col_major> bf[4];
      wmma::load_matrix_sync(af[0], &Ac[(wm*32    )*72 + ks], 72);
      wmma::load_matrix_sync(af[1], &Ac[(wm*32 + 16)*72 + ks], 72);
      #pragma unroll
      for (int c=0;c<4;c++)
        wmma::load_matrix_sync(bf[c], &Bc[(wn*64 + c*16)*72 + ks], 72);
      #pragma unroll
      for (int r=0;r<2;r++)
        #pragma unroll
        for (int c=0;c<4;c++)
          wmma::mma_sync(cf[r][c], af[r], bf[c], cf[r][c]);
    }
    __syncthreads();
  }
  #pragma unroll
  for (int r=0;r<2;r++)
    #pragma unroll
    for (int c=0;c<4;c++)
      wmma::store_matrix_sync(&Cs[(wm*32 + r*16)*132 + wn*64 + c*16], cf[r][c],
                              132, wmma::mem_row_major);
  __syncthreads();

  if (mode == 0) {
    #pragma unroll
    for (int i=0;i<8;i++){
      int idx = i*256 + tid;
      int row = idx >> 4, jq = idx & 15;
      int j = jq*4;
      float4 ya = *(const float4*)&Cs[row*132 + j];
      float4 yb = *(const float4*)&Cs[row*132 + 64 + j];
      float4 ba = *(const float4*)&bias[e0 + j];
      float4 bbv= *(const float4*)&bias[512 + e0 + j];
      float ox = (ya.x + ba.x) * (1.f/(1.f+expf(-(yb.x+bbv.x))));
      float oy = (ya.y + ba.y) * (1.f/(1.f+expf(-(yb.y+bbv.y))));
      float oz = (ya.z + ba.z) * (1.f/(1.f+expf(-(yb.z+bbv.z))));
      float ow = (ya.w + ba.w) * (1.f/(1.f+expf(-(yb.w+bbv.w))));
      __half2* p = (__half2*)&g_gluh[(size_t)(t0+row)*512 + e0 + j];
      p[0] = __floats2half2_rn(ox, oy);
      p[1] = __floats2half2_rn(oz, ow);
    }
  } else {
    #pragma unroll
    for (int i=0;i<16;i++){
      int idx = i*256 + tid;
      int row = idx >> 5, jq = idx & 31;
      int j = jq*4;
      size_t o = (size_t)(t0+row)*512 + e0 + j;
      float4 cv = *(const float4*)&Cs[row*132 + j];
      float4 mv = *(const float4*)&g_mix[o];
      float4 lb4= *(const float4*)&bias[e0 + j];
      float4 ov;
      ov.x = mv.x + cv.x + lb4.x;
      ov.y = mv.y + cv.y + lb4.y;
      ov.z = mv.z + cv.z + lb4.z;
      ov.w = mv.w + cv.w + lb4.w;
      *(float4*)&extout[o] = ov;
    }
  }
}

// ---------------- K6: fused depthwise conv + LN2 + gelu -> acth ----------------
// grid (Ln/32, Bn), 256 thr. smem: gsh 62x512 fp16 (63488) | dw_s 32x512 f32 (65536)
// | red 32x8 f32 (1024) | ms/is 2x32 f32 (256)  -> 130304 B
#define DW_SMEM 130304
__global__ void __launch_bounds__(256) k_dwln(
    const float* __restrict__ dww, const float* __restrict__ dwb,
    const float* __restrict__ g2, const float* __restrict__ b2){
  extern __shared__ char dsm[];
  __half* gsh  = (__half*)dsm;                 // 62 x 512
  float*  dw_s = (float*)(dsm + 63488);        // 32 x 512
  float*  red  = (float*)(dsm + 129024);       // 32 x 8
  float*  ms   = (float*)(dsm + 130048);       // 32
  float*  is   = ms + 32;                      // 32
  const int l0 = blockIdx.x*32, b = blockIdx.y;
  const int tid = threadIdx.x;

  #pragma unroll
  for (int i=0;i<16;i++){
    int idx=i*256+tid;
    if (idx < 3968){
      int row = idx>>6, u = idx&63;
      int l = l0-15+row;
      uint4 v = make_uint4(0u,0u,0u,0u);
      if (l>=0 && l<Ln) v = *(const uint4*)&g_gluh[((size_t)(b*Ln+l))*512 + u*8];
      *(uint4*)&gsh[row*512+u*8] = v;
    }
  }
  __syncthreads();
  #pragma unroll
  for (int p=0;p<2;p++){
    int ch = p*256 + tid;
    float w[31];
    #pragma unroll
    for (int j=0;j<31;j++) w[j] = dww[ch*31+j];
    float bias = dwb[ch];
    for (int tok=0;tok<32;tok++){
      float acc = bias;
      #pragma unroll
      for (int j=0;j<31;j++)
        acc += __half2float(gsh[(tok+j)*512+ch]) * w[j];
      dw_s[tok*512+ch] = acc;
    }
  }
  __syncthreads();
  const int tok = tid>>3, g = tid&7;
  float s=0.f;
  #pragma unroll 8
  for (int i=0;i<64;i++) s += dw_s[tok*512 + g + i*8];
  red[tok*8+g] = s;
  __syncthreads();
  float mean=0.f;
  #pragma unroll
  for (int k=0;k<8;k++) mean += red[tok*8+k];
  mean *= (1.f/512.f);
  __syncthreads();
  float q=0.f;
  #pragma unroll 8
  for (int i=0;i<64;i++){ float d = dw_s[tok*512 + g + i*8] - mean; q += d*d; }
  red[tok*8+g] = q;
  __syncthreads();
  float var=0.f;
  #pragma unroll
  for (int k=0;k<8;k++) var += red[tok*8+k];
  float inv = rsqrtf(var*(1.f/512.f) + 1e-5f);
  if (g==0){ ms[tok]=mean; is[tok]=inv; }
  __syncthreads();
  for (int i=0;i<64;i++){
    int idx = i*256 + tid;
    int t2 = idx>>9, c = idx&511;
    float v = (dw_s[idx]-ms[t2])*is[t2]*g2[c] + b2[c];
    g_acth[((size_t)(b*Ln + l0+t2))*512 + c] = __float2half_rn(gelu_f(v));
  }
}

// ---------------- launch ----------------
extern "C" void kernel_launch(void* const* d_in, const int* in_sizes, int n_in,
                              void* d_out, int out_size) {
  const float* x      = (const float*)d_in[0];
  const float* w1f1w  = (const float*)d_in[1];
  const float* w1f1b  = (const float*)d_in[2];
  const float* w1f2w  = (const float*)d_in[3];
  const float* w1f2b  = (const float*)d_in[4];
  const float* w2f1w  = (const float*)d_in[5];
  const float* w2f1b  = (const float*)d_in[6];
  const float* w2f2w  = (const float*)d_in[7];
  const float* w2f2b  = (const float*)d_in[8];
  const float* lnmg   = (const float*)d_in[9];
  const float* lnmb   = (const float*)d_in[10];
  const float* ln1g   = (const float*)d_in[11];
  const float* ln1b   = (const float*)d_in[12];
  const float* bw     = (const float*)d_in[13];
  const float* bb     = (const float*)d_in[14];
  const float* dww    = (const float*)d_in[15];
  const float* dwb    = (const float*)d_in[16];
  const float* ln2g   = (const float*)d_in[17];
  const float* ln2b   = (const float*)d_in[18];
  const float* lw     = (const float*)d_in[19];
  const float* lb     = (const float*)d_in[20];
  float* out = (float*)d_out;

  cudaFuncSetAttribute(k_pmlpA, cudaFuncAttributeMaxDynamicSharedMemorySize, PA_SMEM);
  cudaFuncSetAttribute(k_pmlpB, cudaFuncAttributeMaxDynamicSharedMemorySize, PA_SMEM);
  cudaFuncSetAttribute(k_hgemm, cudaFuncAttributeMaxDynamicSharedMemorySize, HG_SMEM);
  cudaFuncSetAttribute(k_dwln,  cudaFuncAttributeMaxDynamicSharedMemorySize, DW_SMEM);

  k_prep<<<41216, 256>>>(x, w1f1w, w2f1w, w1f2w, w2f2w, bw, lw);
  k_pmlpA<<<dim3(16, 64), 256, PA_SMEM>>>(x, w1f1b, w2f1b);
  k_pmlpB<<<dim3(16, 128), 256, PA_SMEM>>>(w1f2b, w2f2b);
  k_gemm1w<<<dim3(BMn, 8), 256>>>();
  k_red1<<<4096, 256>>>();
  k_gemm2w<<<dim3(16, BMn), 256>>>();
  k_lnmix<<<Tn, 128>>>(lnmg, lnmb, ln1g, ln1b);
  k_hgemm<<<dim3(Tn/128, 8), 256, HG_SMEM>>>(0, bb, nullptr);
  k_dwln<<<dim3(Ln/32, Bn), 256, DW_SMEM>>>(dww, dwb, ln2g, ln2b);
  k_hgemm<<<dim3(Tn/128, 4), 256, HG_SMEM>>>(1, lb, out);
}